// round 4
// baseline (speedup 1.0000x reference)
#include <cuda_runtime.h>
#include <math.h>

#define B_  8
#define T_  512
#define F_  1024
#define G4  4096           // 4*F
#define V_  32000
#define M_  (B_*T_)        // 4096 rows

// ---------------- scratch (device globals; no allocation allowed) ----------
__device__ float g_xW[(size_t)M_ * G4];    // 64 MB : x@Wx + b, per (b,t) row
__device__ float g_WhT[(size_t)G4 * F_];   // 16 MB : Wh transposed [4F][F]
__device__ float g_hs[(size_t)M_ * F_];    // 16 MB : all hidden states
__device__ float g_h[2][B_ * F_];          // ping-pong hidden state
__device__ float g_c[B_ * F_];             // cell state

// ---------------- init ------------------------------------------------------
__global__ void init_state() {
    int i = blockIdx.x * blockDim.x + threadIdx.x;
    if (i < B_ * F_) {
        g_h[0][i] = 0.f;
        g_h[1][i] = 0.f;
        g_c[i]    = 0.f;
    }
}

// ---------------- Wh transpose: [F, 4F] -> [4F, F] --------------------------
__global__ void transpose_wh(const float* __restrict__ Wh) {
    __shared__ float tile[32][33];
    int n = blockIdx.x * 32 + threadIdx.x;   // 4F dim
    int k = blockIdx.y * 32 + threadIdx.y;   // F dim
    tile[threadIdx.y][threadIdx.x] = Wh[(size_t)k * G4 + n];
    __syncthreads();
    int n2 = blockIdx.x * 32 + threadIdx.y;
    int k2 = blockIdx.y * 32 + threadIdx.x;
    g_WhT[(size_t)n2 * F_ + k2] = tile[threadIdx.x][threadIdx.y];
}

// ---------------- tiled SGEMM: C[M,N] = A[M,K] @ B[K,N] + bias --------------
// BM=BN=128, BK=16, 256 threads, 8x8 micro-tile.
// gather=1: A row m comes from embed[tokens[m]] (embedding lookup fused in).
__global__ __launch_bounds__(256, 2)
void sgemm(const float* __restrict__ A, const int* __restrict__ tokens,
           const float* __restrict__ Bm, const float* __restrict__ bias,
           float* __restrict__ C, int N, int K, int gather)
{
    __shared__ float As[16][128];   // transposed: As[k][m]
    __shared__ float Bs[16][128];

    const int tid = threadIdx.x;
    const int tx = tid & 15;        // 16 col groups
    const int ty = tid >> 4;        // 16 row groups
    const int rowBase = blockIdx.y * 128;
    const int colBase = blockIdx.x * 128;

    float acc[8][8];
#pragma unroll
    for (int i = 0; i < 8; i++)
#pragma unroll
        for (int j = 0; j < 8; j++) acc[i][j] = 0.f;

    for (int k0 = 0; k0 < K; k0 += 16) {
        // load A tile (128 rows x 16 k) -> transposed smem
#pragma unroll
        for (int i = 0; i < 2; i++) {
            int f  = tid + i * 256;          // 512 float4 total
            int r  = f >> 2;
            int c4 = f & 3;
            int m  = rowBase + r;
            const float* arow = gather ? (A + (size_t)tokens[m] * K)
                                       : (A + (size_t)m * K);
            float4 v = *(const float4*)(arow + k0 + c4 * 4);
            As[c4 * 4 + 0][r] = v.x;
            As[c4 * 4 + 1][r] = v.y;
            As[c4 * 4 + 2][r] = v.z;
            As[c4 * 4 + 3][r] = v.w;
        }
        // load B tile (16 k x 128 cols)
#pragma unroll
        for (int i = 0; i < 2; i++) {
            int f  = tid + i * 256;
            int r  = f >> 5;
            int c4 = f & 31;
            *(float4*)&Bs[r][c4 * 4] =
                *(const float4*)(Bm + (size_t)(k0 + r) * N + colBase + c4 * 4);
        }
        __syncthreads();

#pragma unroll
        for (int kk = 0; kk < 16; kk++) {
            float a[8], bb[8];
#pragma unroll
            for (int i = 0; i < 8; i++) a[i] = As[kk][ty * 8 + i];
#pragma unroll
            for (int j = 0; j < 8; j++) bb[j] = Bs[kk][tx * 8 + j];
#pragma unroll
            for (int i = 0; i < 8; i++)
#pragma unroll
                for (int j = 0; j < 8; j++) acc[i][j] += a[i] * bb[j];
        }
        __syncthreads();
    }

#pragma unroll
    for (int i = 0; i < 8; i++) {
        size_t m = (size_t)(rowBase + ty * 8 + i);
#pragma unroll
        for (int j = 0; j < 8; j += 4) {
            int c = colBase + tx * 8 + j;
            float4 v;
            v.x = acc[i][j + 0] + bias[c + 0];
            v.y = acc[i][j + 1] + bias[c + 1];
            v.z = acc[i][j + 2] + bias[c + 2];
            v.w = acc[i][j + 3] + bias[c + 3];
            *(float4*)(C + m * N + c) = v;
        }
    }
}

// ---------------- fused LSTM step -------------------------------------------
// One warp per hidden column j (1024 warps total). Each warp computes the
// 4 gate dot-products against all 8 batches (h @ Wh columns j, F+j, 2F+j, 3F+j),
// butterfly-reduces, then applies the pointwise LSTM update in the same kernel.
__device__ __forceinline__ float sigmoidf_(float x) {
    return 1.f / (1.f + __expf(-x));
}

__global__ __launch_bounds__(256)
void lstm_step(int t) {
    const int warp = (blockIdx.x << 3) + (threadIdx.x >> 5);  // 0..1023 = column j
    const int lane = threadIdx.x & 31;
    const int j = warp;

    const float* __restrict__ hin  = g_h[t & 1];
    float* __restrict__ hout       = g_h[(t + 1) & 1];
    const float* __restrict__ w0 = g_WhT + (size_t)(0 * F_ + j) * F_;
    const float* __restrict__ w1 = g_WhT + (size_t)(1 * F_ + j) * F_;
    const float* __restrict__ w2 = g_WhT + (size_t)(2 * F_ + j) * F_;
    const float* __restrict__ w3 = g_WhT + (size_t)(3 * F_ + j) * F_;

    float acc0[8], acc1[8], acc2[8], acc3[8];
#pragma unroll
    for (int b = 0; b < 8; b++) { acc0[b] = acc1[b] = acc2[b] = acc3[b] = 0.f; }

#pragma unroll 2
    for (int p = 0; p < 8; p++) {
        int k = (p * 32 + lane) * 4;          // float4 per lane, coalesced
        float4 wi = *(const float4*)(w0 + k);
        float4 wf = *(const float4*)(w1 + k);
        float4 wg = *(const float4*)(w2 + k);
        float4 wo = *(const float4*)(w3 + k);
#pragma unroll
        for (int b = 0; b < 8; b++) {
            float4 hv = *(const float4*)(hin + b * F_ + k);
            acc0[b] += wi.x * hv.x; acc0[b] += wi.y * hv.y;
            acc0[b] += wi.z * hv.z; acc0[b] += wi.w * hv.w;
            acc1[b] += wf.x * hv.x; acc1[b] += wf.y * hv.y;
            acc1[b] += wf.z * hv.z; acc1[b] += wf.w * hv.w;
            acc2[b] += wg.x * hv.x; acc2[b] += wg.y * hv.y;
            acc2[b] += wg.z * hv.z; acc2[b] += wg.w * hv.w;
            acc3[b] += wo.x * hv.x; acc3[b] += wo.y * hv.y;
            acc3[b] += wo.z * hv.z; acc3[b] += wo.w * hv.w;
        }
    }

    // butterfly reduce: every lane ends with the full sums
#pragma unroll
    for (int off = 16; off; off >>= 1) {
#pragma unroll
        for (int b = 0; b < 8; b++) {
            acc0[b] += __shfl_xor_sync(0xffffffffu, acc0[b], off);
            acc1[b] += __shfl_xor_sync(0xffffffffu, acc1[b], off);
            acc2[b] += __shfl_xor_sync(0xffffffffu, acc2[b], off);
            acc3[b] += __shfl_xor_sync(0xffffffffu, acc3[b], off);
        }
    }

    if (lane < 8) {
        // lane b handles batch b; select its sums via predicated moves
        float s0 = acc0[0], s1 = acc1[0], s2 = acc2[0], s3 = acc3[0];
#pragma unroll
        for (int b = 1; b < 8; b++) {
            if (lane == b) { s0 = acc0[b]; s1 = acc1[b]; s2 = acc2[b]; s3 = acc3[b]; }
        }
        int b = lane;
        size_t row = (size_t)(b * T_ + t) * G4;
        float zi = s0 + g_xW[row + 0 * F_ + j];
        float zf = s1 + g_xW[row + 1 * F_ + j];
        float zg = s2 + g_xW[row + 2 * F_ + j];
        float zo = s3 + g_xW[row + 3 * F_ + j];

        float si = sigmoidf_(zi);
        float sf = sigmoidf_(zf);
        float so = sigmoidf_(zo);
        float cn = sf * g_c[b * F_ + j] + si * tanhf(zg);
        float hn = so * tanhf(cn);

        g_c[b * F_ + j]   = cn;
        hout[b * F_ + j]  = hn;
        g_hs[(size_t)(b * T_ + t) * F_ + j] = hn;
    }
}

// ---------------- launch -----------------------------------------------------
extern "C" void kernel_launch(void* const* d_in, const int* in_sizes, int n_in,
                              void* d_out, int out_size) {
    const int*   tokens = (const int*)  d_in[0];
    const float* embed  = (const float*)d_in[1];
    const float* Wx     = (const float*)d_in[2];
    const float* Wh     = (const float*)d_in[3];
    const float* bias   = (const float*)d_in[4];
    const float* Wd     = (const float*)d_in[5];
    const float* bd     = (const float*)d_in[6];
    float* out = (float*)d_out;

    float *xW = nullptr, *hs = nullptr;
    cudaGetSymbolAddress((void**)&xW, g_xW);
    cudaGetSymbolAddress((void**)&hs, g_hs);

    // zero h, c
    init_state<<<(B_ * F_ + 255) / 256, 256>>>();

    // Wh -> WhT
    transpose_wh<<<dim3(G4 / 32, F_ / 32), dim3(32, 32)>>>(Wh);

    // xW = embed[tokens] @ Wx + b   (embedding gather fused into A load)
    sgemm<<<dim3(G4 / 128, M_ / 128), 256>>>(embed, tokens, Wx, bias, xW,
                                             G4, F_, 1);

    // 512 sequential fused LSTM steps
    for (int t = 0; t < T_; t++) {
        lstm_step<<<128, 256>>>(t);
    }

    // logits = hs @ Wd + bd
    sgemm<<<dim3(V_ / 128, M_ / 128), 256>>>(hs, nullptr, Wd, bd, out,
                                             V_, F_, 0);
}

// round 8
// speedup vs baseline: 1.6584x; 1.6584x over previous
#include <cuda_runtime.h>
#include <cuda_bf16.h>
#include <math.h>
#include <stdint.h>

#define B_  8
#define T_  512
#define F_  1024
#define G4  4096           // 4*F
#define V_  32000
#define M_  (B_*T_)        // 4096 rows
#define K_  1024

// ---------------- scratch (device globals; no allocation allowed) ----------
__device__ float g_xW[(size_t)M_ * G4];              // 64 MB : x@Wx + b
__device__ float g_WhT[(size_t)G4 * F_];             // 16 MB : Wh^T [4F][F]
__device__ float g_hs[(size_t)M_ * F_];              // 16 MB : hidden states
__device__ float g_h[2][B_ * F_];
__device__ float g_c[B_ * F_];
// bf16 split operands for tensor-core GEMMs
__device__ __nv_bfloat16 g_Ahi[(size_t)M_ * K_];     // 8 MB (x, then hs)
__device__ __nv_bfloat16 g_Alo[(size_t)M_ * K_];     // 8 MB
__device__ __nv_bfloat16 g_WxT_hi[(size_t)G4 * K_];  // 8 MB  [4F][F]
__device__ __nv_bfloat16 g_WxT_lo[(size_t)G4 * K_];  // 8 MB
__device__ __nv_bfloat16 g_WdT_hi[(size_t)V_ * K_];  // 64 MB [V][F]
__device__ __nv_bfloat16 g_WdT_lo[(size_t)V_ * K_];  // 64 MB

// ======================= PTX helpers (sm_103-safe: no tcgen05) ==============
__device__ __forceinline__ uint32_t smem_u32(const void* p) {
    uint32_t a;
    asm("{ .reg .u64 t; cvta.to.shared.u64 t, %1; cvt.u32.u64 %0, t; }"
        : "=r"(a) : "l"(p));
    return a;
}
__device__ __forceinline__ void cp16(uint32_t s, const void* g) {
    asm volatile("cp.async.cg.shared.global [%0], [%1], 16;"
                 :: "r"(s), "l"(g) : "memory");
}
#define CP_COMMIT() asm volatile("cp.async.commit_group;" ::: "memory")
#define CP_WAIT(n)  asm volatile("cp.async.wait_group %0;" :: "n"(n) : "memory")

__device__ __forceinline__ void ldsm4(uint32_t* r, uint32_t addr) {
    asm volatile("ldmatrix.sync.aligned.m8n8.x4.shared.b16 {%0,%1,%2,%3}, [%4];"
                 : "=r"(r[0]), "=r"(r[1]), "=r"(r[2]), "=r"(r[3]) : "r"(addr));
}
__device__ __forceinline__ void mma16816(float* c, const uint32_t* a,
                                         const uint32_t* b) {
    asm volatile(
        "mma.sync.aligned.m16n8k16.row.col.f32.bf16.bf16.f32 "
        "{%0,%1,%2,%3}, {%4,%5,%6,%7}, {%8,%9}, {%0,%1,%2,%3};"
        : "+f"(c[0]), "+f"(c[1]), "+f"(c[2]), "+f"(c[3])
        : "r"(a[0]), "r"(a[1]), "r"(a[2]), "r"(a[3]), "r"(b[0]), "r"(b[1]));
}

// ======================= prep kernels =======================================
__global__ void init_state() {
    int i = blockIdx.x * blockDim.x + threadIdx.x;
    if (i < B_ * F_) { g_h[0][i] = 0.f; g_h[1][i] = 0.f; g_c[i] = 0.f; }
}

__global__ void transpose_wh(const float* __restrict__ Wh) {
    __shared__ float tile[32][33];
    int n = blockIdx.x * 32 + threadIdx.x;
    int k = blockIdx.y * 32 + threadIdx.y;
    tile[threadIdx.y][threadIdx.x] = Wh[(size_t)k * G4 + n];
    __syncthreads();
    int n2 = blockIdx.x * 32 + threadIdx.y;
    int k2 = blockIdx.y * 32 + threadIdx.x;
    g_WhT[(size_t)n2 * F_ + k2] = tile[threadIdx.x][threadIdx.y];
}

// src fp32 [rows x 1024] (optionally gathered through tokens) -> hi/lo bf16
__global__ void split_rows(const float* __restrict__ src,
                           const int* __restrict__ tokens,
                           __nv_bfloat16* __restrict__ hi,
                           __nv_bfloat16* __restrict__ lo, int gather) {
    size_t idx = (size_t)blockIdx.x * blockDim.x + threadIdx.x;
    if (idx >= (size_t)M_ * K_) return;
    size_t row = idx >> 10, col = idx & 1023;
    const float* s = gather ? (src + (size_t)tokens[row] * K_)
                            : (src + row * K_);
    float x = s[col];
    __nv_bfloat16 h = __float2bfloat16(x);
    hi[idx] = h;
    lo[idx] = __float2bfloat16(x - __bfloat162float(h));
}

// W fp32 [1024 x N] -> WT hi/lo bf16 [N x 1024]
__global__ void transpose_split(const float* __restrict__ W,
                                __nv_bfloat16* __restrict__ Thi,
                                __nv_bfloat16* __restrict__ Tlo, int N) {
    __shared__ float tile[32][33];
    int n = blockIdx.x * 32 + threadIdx.x;
    int k = blockIdx.y * 32 + threadIdx.y;
    tile[threadIdx.y][threadIdx.x] = W[(size_t)k * N + n];
    __syncthreads();
    int n2 = blockIdx.x * 32 + threadIdx.y;
    int k2 = blockIdx.y * 32 + threadIdx.x;
    float x = tile[threadIdx.x][threadIdx.y];
    __nv_bfloat16 h = __float2bfloat16(x);
    size_t o = (size_t)n2 * K_ + k2;
    Thi[o] = h;
    Tlo[o] = __float2bfloat16(x - __bfloat162float(h));
}

// ======================= mma.sync bf16-split GEMM ===========================
// C[M,N] = A[M,1024] @ B[N,1024]^T + bias.  A,B given as hi/lo bf16, K-major.
// CTA tile 128x128, BK=32, 8 warps (2m x 4n), warp tile 64x32.
// 3-stage cp.async pipeline; XOR-swizzled smem; ldmatrix (non-trans) both ops.
#define BK      32
#define NCHUNK  (K_ / BK)          // 32
#define NSTAGE  3
#define TILE_B  (128 * 64)         // 8 KB: 128 rows x 32 bf16 (64B/row)
#define STAGE_B (4 * TILE_B)       // 32 KB: Ahi, Alo, Bhi, Blo
#define GEMM_SMEM (NSTAGE * STAGE_B)   // 96 KB

// swizzled byte offset within one tile for (row, 16B-unit)
__device__ __forceinline__ uint32_t sw_off(int r, int u) {
    return (uint32_t)(r * 64 + ((u ^ ((r >> 1) & 3)) << 4));
}

__device__ __forceinline__ void load_stage(const __nv_bfloat16* __restrict__ Ahi,
                                           const __nv_bfloat16* __restrict__ Alo,
                                           const __nv_bfloat16* __restrict__ Bhi,
                                           const __nv_bfloat16* __restrict__ Blo,
                                           int rowBase, int colBase, int k0,
                                           uint32_t stage, int tid) {
#pragma unroll
    for (int i = 0; i < 2; i++) {
        int e = tid + i * 256;               // 0..511
        int r = e >> 2, u = e & 3;
        uint32_t so = sw_off(r, u);
        size_t goA = (size_t)(rowBase + r) * K_ + k0 + u * 8;
        size_t goB = (size_t)(colBase + r) * K_ + k0 + u * 8;
        cp16(stage + 0 * TILE_B + so, Ahi + goA);
        cp16(stage + 1 * TILE_B + so, Alo + goA);
        cp16(stage + 2 * TILE_B + so, Bhi + goB);
        cp16(stage + 3 * TILE_B + so, Blo + goB);
    }
}

__global__ __launch_bounds__(256, 1)
void gemm_bf16s(const __nv_bfloat16* __restrict__ Ahi,
                const __nv_bfloat16* __restrict__ Alo,
                const __nv_bfloat16* __restrict__ Bhi,
                const __nv_bfloat16* __restrict__ Blo,
                const float* __restrict__ bias,
                float* __restrict__ C, int N)
{
    extern __shared__ char smem[];
    const uint32_t sbase = smem_u32(smem);
    const int tid  = threadIdx.x;
    const int wid  = tid >> 5;
    const int lane = tid & 31;
    const int warp_m = wid & 1;          // 2 warp-rows of 64
    const int warp_n = wid >> 1;         // 4 warp-cols of 32
    const int rowBase = blockIdx.x * 128;   // m-tile fastest -> B reuse in L2
    const int colBase = blockIdx.y * 128;

    float acc[4][4][4];
#pragma unroll
    for (int i = 0; i < 4; i++)
#pragma unroll
        for (int j = 0; j < 4; j++)
#pragma unroll
            for (int q = 0; q < 4; q++) acc[i][j][q] = 0.f;

    // ldmatrix per-lane address components
    const int a_row = warp_m * 64 + (lane & 15);      // + i*16
    const int a_uo  = lane >> 4;                      // + 2s
    const int b_row = warp_n * 32 + ((lane >> 4) << 3) + (lane & 7);  // + p*16
    const int b_uo  = (lane >> 3) & 1;                // + 2s

    // prologue: stages 0..NSTAGE-2
#pragma unroll
    for (int s = 0; s < NSTAGE - 1; s++) {
        load_stage(Ahi, Alo, Bhi, Blo, rowBase, colBase, s * BK,
                   sbase + s * STAGE_B, tid);
        CP_COMMIT();
    }

    for (int k = 0; k < NCHUNK; k++) {
        CP_WAIT(NSTAGE - 2);
        __syncthreads();
        if (k + NSTAGE - 1 < NCHUNK) {
            load_stage(Ahi, Alo, Bhi, Blo, rowBase, colBase,
                       (k + NSTAGE - 1) * BK,
                       sbase + ((k + NSTAGE - 1) % NSTAGE) * STAGE_B, tid);
        }
        CP_COMMIT();

        const uint32_t st = sbase + (k % NSTAGE) * STAGE_B;
#pragma unroll
        for (int s = 0; s < 2; s++) {                 // two k16 steps per chunk
            uint32_t ahi[4][4], alo[4][4], bhi[2][4], blo[2][4];
#pragma unroll
            for (int i = 0; i < 4; i++) {
                int r = a_row + i * 16;
                uint32_t off = sw_off(r, 2 * s + a_uo);
                ldsm4(ahi[i], st + 0 * TILE_B + off);
                ldsm4(alo[i], st + 1 * TILE_B + off);
            }
#pragma unroll
            for (int p = 0; p < 2; p++) {             // each x4 = two n8 frags
                int r = b_row + p * 16;
                uint32_t off = sw_off(r, 2 * s + b_uo);
                ldsm4(bhi[p], st + 2 * TILE_B + off);
                ldsm4(blo[p], st + 3 * TILE_B + off);
            }
#pragma unroll
            for (int i = 0; i < 4; i++) {
#pragma unroll
                for (int j = 0; j < 4; j++) {
                    const uint32_t* bh = &bhi[j >> 1][(j & 1) * 2];
                    const uint32_t* bl = &blo[j >> 1][(j & 1) * 2];
                    mma16816(acc[i][j], ahi[i], bh);   // hi*hi
                    mma16816(acc[i][j], ahi[i], bl);   // hi*lo
                    mma16816(acc[i][j], alo[i], bh);   // lo*hi
                }
            }
        }
    }

    // epilogue: direct global stores + bias
#pragma unroll
    for (int i = 0; i < 4; i++) {
        int row0 = rowBase + warp_m * 64 + i * 16 + (lane >> 2);
#pragma unroll
        for (int j = 0; j < 4; j++) {
            int col = colBase + warp_n * 32 + j * 8 + (lane & 3) * 2;
            float b0 = bias[col], b1 = bias[col + 1];
            float2 v0 = make_float2(acc[i][j][0] + b0, acc[i][j][1] + b1);
            float2 v1 = make_float2(acc[i][j][2] + b0, acc[i][j][3] + b1);
            *(float2*)(C + (size_t)row0 * N + col)       = v0;
            *(float2*)(C + (size_t)(row0 + 8) * N + col) = v1;
        }
    }
}

// ======================= fused LSTM step (unchanged) ========================
__device__ __forceinline__ float sigmoidf_(float x) {
    return 1.f / (1.f + __expf(-x));
}

__global__ __launch_bounds__(256)
void lstm_step(int t) {
    const int warp = (blockIdx.x << 3) + (threadIdx.x >> 5);
    const int lane = threadIdx.x & 31;
    const int j = warp;

    const float* __restrict__ hin  = g_h[t & 1];
    float* __restrict__ hout       = g_h[(t + 1) & 1];
    const float* __restrict__ w0 = g_WhT + (size_t)(0 * F_ + j) * F_;
    const float* __restrict__ w1 = g_WhT + (size_t)(1 * F_ + j) * F_;
    const float* __restrict__ w2 = g_WhT + (size_t)(2 * F_ + j) * F_;
    const float* __restrict__ w3 = g_WhT + (size_t)(3 * F_ + j) * F_;

    float acc0[8], acc1[8], acc2[8], acc3[8];
#pragma unroll
    for (int b = 0; b < 8; b++) { acc0[b] = acc1[b] = acc2[b] = acc3[b] = 0.f; }

#pragma unroll 2
    for (int p = 0; p < 8; p++) {
        int k = (p * 32 + lane) * 4;
        float4 wi = *(const float4*)(w0 + k);
        float4 wf = *(const float4*)(w1 + k);
        float4 wg = *(const float4*)(w2 + k);
        float4 wo = *(const float4*)(w3 + k);
#pragma unroll
        for (int b = 0; b < 8; b++) {
            float4 hv = *(const float4*)(hin + b * F_ + k);
            acc0[b] += wi.x * hv.x; acc0[b] += wi.y * hv.y;
            acc0[b] += wi.z * hv.z; acc0[b] += wi.w * hv.w;
            acc1[b] += wf.x * hv.x; acc1[b] += wf.y * hv.y;
            acc1[b] += wf.z * hv.z; acc1[b] += wf.w * hv.w;
            acc2[b] += wg.x * hv.x; acc2[b] += wg.y * hv.y;
            acc2[b] += wg.z * hv.z; acc2[b] += wg.w * hv.w;
            acc3[b] += wo.x * hv.x; acc3[b] += wo.y * hv.y;
            acc3[b] += wo.z * hv.z; acc3[b] += wo.w * hv.w;
        }
    }

#pragma unroll
    for (int off = 16; off; off >>= 1) {
#pragma unroll
        for (int b = 0; b < 8; b++) {
            acc0[b] += __shfl_xor_sync(0xffffffffu, acc0[b], off);
            acc1[b] += __shfl_xor_sync(0xffffffffu, acc1[b], off);
            acc2[b] += __shfl_xor_sync(0xffffffffu, acc2[b], off);
            acc3[b] += __shfl_xor_sync(0xffffffffu, acc3[b], off);
        }
    }

    if (lane < 8) {
        float s0 = acc0[0], s1 = acc1[0], s2 = acc2[0], s3 = acc3[0];
#pragma unroll
        for (int b = 1; b < 8; b++) {
            if (lane == b) { s0 = acc0[b]; s1 = acc1[b]; s2 = acc2[b]; s3 = acc3[b]; }
        }
        int b = lane;
        size_t row = (size_t)(b * T_ + t) * G4;
        float zi = s0 + g_xW[row + 0 * F_ + j];
        float zf = s1 + g_xW[row + 1 * F_ + j];
        float zg = s2 + g_xW[row + 2 * F_ + j];
        float zo = s3 + g_xW[row + 3 * F_ + j];

        float si = sigmoidf_(zi);
        float sf = sigmoidf_(zf);
        float so = sigmoidf_(zo);
        float cn = sf * g_c[b * F_ + j] + si * tanhf(zg);
        float hn = so * tanhf(cn);

        g_c[b * F_ + j]   = cn;
        hout[b * F_ + j]  = hn;
        g_hs[(size_t)(b * T_ + t) * F_ + j] = hn;
    }
}

// ======================= launch =============================================
extern "C" void kernel_launch(void* const* d_in, const int* in_sizes, int n_in,
                              void* d_out, int out_size) {
    const int*   tokens = (const int*)  d_in[0];
    const float* embed  = (const float*)d_in[1];
    const float* Wx     = (const float*)d_in[2];
    const float* Wh     = (const float*)d_in[3];
    const float* bias   = (const float*)d_in[4];
    const float* Wd     = (const float*)d_in[5];
    const float* bd     = (const float*)d_in[6];
    float* out = (float*)d_out;

    float *xW = nullptr, *hs = nullptr;
    __nv_bfloat16 *ahi = nullptr, *alo = nullptr;
    __nv_bfloat16 *wxh = nullptr, *wxl = nullptr, *wdh = nullptr, *wdl = nullptr;
    cudaGetSymbolAddress((void**)&xW,  g_xW);
    cudaGetSymbolAddress((void**)&hs,  g_hs);
    cudaGetSymbolAddress((void**)&ahi, g_Ahi);
    cudaGetSymbolAddress((void**)&alo, g_Alo);
    cudaGetSymbolAddress((void**)&wxh, g_WxT_hi);
    cudaGetSymbolAddress((void**)&wxl, g_WxT_lo);
    cudaGetSymbolAddress((void**)&wdh, g_WdT_hi);
    cudaGetSymbolAddress((void**)&wdl, g_WdT_lo);

    cudaFuncSetAttribute(gemm_bf16s,
                         cudaFuncAttributeMaxDynamicSharedMemorySize, GEMM_SMEM);

    init_state<<<(B_ * F_ + 255) / 256, 256>>>();
    transpose_wh<<<dim3(G4 / 32, F_ / 32), dim3(32, 32)>>>(Wh);

    // ---- input path: x = embed[tokens]; xW = x @ Wx + b ----
    split_rows<<<(M_ * K_ + 255) / 256, 256>>>(embed, tokens, ahi, alo, 1);
    transpose_split<<<dim3(G4 / 32, K_ / 32), dim3(32, 32)>>>(Wx, wxh, wxl, G4);
    gemm_bf16s<<<dim3(M_ / 128, G4 / 128), 256, GEMM_SMEM>>>(
        ahi, alo, wxh, wxl, bias, xW, G4);

    // ---- recurrence ----
    for (int t = 0; t < T_; t++) lstm_step<<<128, 256>>>(t);

    // ---- projection: out = hs @ Wd + bd ----
    split_rows<<<(M_ * K_ + 255) / 256, 256>>>(hs, nullptr, ahi, alo, 0);
    transpose_split<<<dim3(V_ / 32, K_ / 32), dim3(32, 32)>>>(Wd, wdh, wdl, V_);
    gemm_bf16s<<<dim3(M_ / 128, V_ / 128), 256, GEMM_SMEM>>>(
        ahi, alo, wdh, wdl, bd, out, V_);
}

// round 9
// speedup vs baseline: 1.9545x; 1.1786x over previous
#include <cuda_runtime.h>
#include <cuda_bf16.h>
#include <math.h>
#include <stdint.h>

#define B_  8
#define T_  512
#define F_  1024
#define G4  4096           // 4*F
#define V_  32000
#define M_  (B_*T_)        // 4096 rows
#define K_  1024
#define LSTM_CTAS 128

// ---------------- scratch (device globals; no allocation allowed) ----------
__device__ float g_xW[(size_t)M_ * G4];              // 64 MB : x@Wx + b
__device__ float g_WhT[(size_t)G4 * F_];             // 16 MB : Wh^T [4F][F]
__device__ float g_h[2][B_ * F_];                    // ping-pong hidden state
__device__ unsigned g_bar;                           // grid barrier counter
// bf16 split operands for tensor-core GEMMs
__device__ __nv_bfloat16 g_Ahi[(size_t)M_ * K_];     // 8 MB (x, then hs)
__device__ __nv_bfloat16 g_Alo[(size_t)M_ * K_];     // 8 MB
__device__ __nv_bfloat16 g_WxT_hi[(size_t)G4 * K_];  // 8 MB  [4F][F]
__device__ __nv_bfloat16 g_WxT_lo[(size_t)G4 * K_];  // 8 MB
__device__ __nv_bfloat16 g_WdT_hi[(size_t)V_ * K_];  // 64 MB [V][F]
__device__ __nv_bfloat16 g_WdT_lo[(size_t)V_ * K_];  // 64 MB

// ======================= PTX helpers (sm_103-safe) ==========================
__device__ __forceinline__ uint32_t smem_u32(const void* p) {
    uint32_t a;
    asm("{ .reg .u64 t; cvta.to.shared.u64 t, %1; cvt.u32.u64 %0, t; }"
        : "=r"(a) : "l"(p));
    return a;
}
__device__ __forceinline__ void cp16(uint32_t s, const void* g) {
    asm volatile("cp.async.cg.shared.global [%0], [%1], 16;"
                 :: "r"(s), "l"(g) : "memory");
}
#define CP_COMMIT() asm volatile("cp.async.commit_group;" ::: "memory")
#define CP_WAIT(n)  asm volatile("cp.async.wait_group %0;" :: "n"(n) : "memory")

__device__ __forceinline__ void ldsm4(uint32_t* r, uint32_t addr) {
    asm volatile("ldmatrix.sync.aligned.m8n8.x4.shared.b16 {%0,%1,%2,%3}, [%4];"
                 : "=r"(r[0]), "=r"(r[1]), "=r"(r[2]), "=r"(r[3]) : "r"(addr));
}
__device__ __forceinline__ void mma16816(float* c, const uint32_t* a,
                                         const uint32_t* b) {
    asm volatile(
        "mma.sync.aligned.m16n8k16.row.col.f32.bf16.bf16.f32 "
        "{%0,%1,%2,%3}, {%4,%5,%6,%7}, {%8,%9}, {%0,%1,%2,%3};"
        : "+f"(c[0]), "+f"(c[1]), "+f"(c[2]), "+f"(c[3])
        : "r"(a[0]), "r"(a[1]), "r"(a[2]), "r"(a[3]), "r"(b[0]), "r"(b[1]));
}
// packed fp32x2 FMA (sm_100+ family, NOT an 'a'-suffixed feature)
__device__ __forceinline__ uint64_t fma2(uint64_t a, uint64_t b, uint64_t c) {
    uint64_t d;
    asm("fma.rn.f32x2 %0, %1, %2, %3;" : "=l"(d) : "l"(a), "l"(b), "l"(c));
    return d;
}
__device__ __forceinline__ float unpack_add(uint64_t a) {
    float lo, hi;
    asm("mov.b64 {%0,%1}, %2;" : "=f"(lo), "=f"(hi) : "l"(a));
    return lo + hi;
}

// ======================= prep kernels =======================================
__global__ void init_state() {
    int i = blockIdx.x * blockDim.x + threadIdx.x;
    if (i < B_ * F_) { g_h[0][i] = 0.f; g_h[1][i] = 0.f; }
    if (i == 0) g_bar = 0u;
}

__global__ void transpose_wh(const float* __restrict__ Wh) {
    __shared__ float tile[32][33];
    int n = blockIdx.x * 32 + threadIdx.x;
    int k = blockIdx.y * 32 + threadIdx.y;
    tile[threadIdx.y][threadIdx.x] = Wh[(size_t)k * G4 + n];
    __syncthreads();
    int n2 = blockIdx.x * 32 + threadIdx.y;
    int k2 = blockIdx.y * 32 + threadIdx.x;
    g_WhT[(size_t)n2 * F_ + k2] = tile[threadIdx.x][threadIdx.y];
}

// embed[tokens] fp32 -> hi/lo bf16 rows
__global__ void split_rows(const float* __restrict__ src,
                           const int* __restrict__ tokens,
                           __nv_bfloat16* __restrict__ hi,
                           __nv_bfloat16* __restrict__ lo) {
    size_t idx = (size_t)blockIdx.x * blockDim.x + threadIdx.x;
    if (idx >= (size_t)M_ * K_) return;
    size_t row = idx >> 10, col = idx & 1023;
    float x = src[(size_t)tokens[row] * K_ + col];
    __nv_bfloat16 h = __float2bfloat16(x);
    hi[idx] = h;
    lo[idx] = __float2bfloat16(x - __bfloat162float(h));
}

// W fp32 [1024 x N] -> WT hi/lo bf16 [N x 1024]
__global__ void transpose_split(const float* __restrict__ W,
                                __nv_bfloat16* __restrict__ Thi,
                                __nv_bfloat16* __restrict__ Tlo, int N) {
    __shared__ float tile[32][33];
    int n = blockIdx.x * 32 + threadIdx.x;
    int k = blockIdx.y * 32 + threadIdx.y;
    tile[threadIdx.y][threadIdx.x] = W[(size_t)k * N + n];
    __syncthreads();
    int n2 = blockIdx.x * 32 + threadIdx.y;
    int k2 = blockIdx.y * 32 + threadIdx.x;
    float x = tile[threadIdx.x][threadIdx.y];
    __nv_bfloat16 h = __float2bfloat16(x);
    size_t o = (size_t)n2 * K_ + k2;
    Thi[o] = h;
    Tlo[o] = __float2bfloat16(x - __bfloat162float(h));
}

// ======================= mma.sync bf16-split GEMM ===========================
// C[M,N] = A[M,1024] @ B[N,1024]^T + bias.  CTA tile 128x128, BK=64,
// 8 warps (2m x 4n), 2-stage cp.async double buffer, register-double-buffered
// ldmatrix fragments, SW128 swizzle on 128B rows.
#define BK      64
#define NCHUNK  (K_ / BK)          // 16
#define TILE_B  (128 * 128)        // 16 KB: 128 rows x 64 bf16 (128B/row)
#define STAGE_B (4 * TILE_B)       // 64 KB: Ahi, Alo, Bhi, Blo
#define NSTAGE  2
#define GEMM_SMEM (NSTAGE * STAGE_B)   // 128 KB

// swizzled byte offset within one tile for (row, 16B-unit u in 0..7)
__device__ __forceinline__ uint32_t sw_off(int r, int u) {
    return (uint32_t)(r * 128 + ((u ^ (r & 7)) << 4));
}

__device__ __forceinline__ void load_stage(const __nv_bfloat16* __restrict__ Ahi,
                                           const __nv_bfloat16* __restrict__ Alo,
                                           const __nv_bfloat16* __restrict__ Bhi,
                                           const __nv_bfloat16* __restrict__ Blo,
                                           int rowBase, int colBase, int k0,
                                           uint32_t stage, int tid) {
#pragma unroll
    for (int i = 0; i < 4; i++) {
        int e = tid + i * 256;               // 0..1023
        int r = e >> 3, u = e & 7;
        uint32_t so = sw_off(r, u);
        size_t goA = (size_t)(rowBase + r) * K_ + k0 + u * 8;
        size_t goB = (size_t)(colBase + r) * K_ + k0 + u * 8;
        cp16(stage + 0 * TILE_B + so, Ahi + goA);
        cp16(stage + 1 * TILE_B + so, Alo + goA);
        cp16(stage + 2 * TILE_B + so, Bhi + goB);
        cp16(stage + 3 * TILE_B + so, Blo + goB);
    }
}

__device__ __forceinline__ void ldsm_all(uint32_t st, int s,
                                         int a_row, int a_uo,
                                         int b_row, int b_uo,
                                         uint32_t (*ahi)[4], uint32_t (*alo)[4],
                                         uint32_t (*bhi)[4], uint32_t (*blo)[4]) {
#pragma unroll
    for (int i = 0; i < 4; i++) {
        int r = a_row + i * 16;
        uint32_t off = sw_off(r, 2 * s + a_uo);
        ldsm4(ahi[i], st + 0 * TILE_B + off);
        ldsm4(alo[i], st + 1 * TILE_B + off);
    }
#pragma unroll
    for (int p = 0; p < 2; p++) {
        int r = b_row + p * 16;
        uint32_t off = sw_off(r, 2 * s + b_uo);
        ldsm4(bhi[p], st + 2 * TILE_B + off);
        ldsm4(blo[p], st + 3 * TILE_B + off);
    }
}

__global__ __launch_bounds__(256, 1)
void gemm_bf16s(const __nv_bfloat16* __restrict__ Ahi,
                const __nv_bfloat16* __restrict__ Alo,
                const __nv_bfloat16* __restrict__ Bhi,
                const __nv_bfloat16* __restrict__ Blo,
                const float* __restrict__ bias,
                float* __restrict__ C, int N)
{
    extern __shared__ char smem[];
    const uint32_t sbase = smem_u32(smem);
    const int tid  = threadIdx.x;
    const int wid  = tid >> 5;
    const int lane = tid & 31;
    const int warp_m = wid & 1;          // 2 warp-rows of 64
    const int warp_n = wid >> 1;         // 4 warp-cols of 32
    const int rowBase = blockIdx.x * 128;   // m fastest -> B-tile reuse in L2
    const int colBase = blockIdx.y * 128;

    float acc[4][4][4];
#pragma unroll
    for (int i = 0; i < 4; i++)
#pragma unroll
        for (int j = 0; j < 4; j++)
#pragma unroll
            for (int q = 0; q < 4; q++) acc[i][j][q] = 0.f;

    const int a_row = warp_m * 64 + (lane & 15);
    const int a_uo  = lane >> 4;
    const int b_row = warp_n * 32 + ((lane >> 4) << 3) + (lane & 7);
    const int b_uo  = (lane >> 3) & 1;

    uint32_t ahi[2][4][4], alo[2][4][4], bhi[2][2][4], blo[2][2][4];

    // prologue: stage 0
    load_stage(Ahi, Alo, Bhi, Blo, rowBase, colBase, 0, sbase, tid);
    CP_COMMIT();

    for (int k = 0; k < NCHUNK; k++) {
        __syncthreads();   // everyone done reading the buffer we're about to fill
        if (k + 1 < NCHUNK) {
            load_stage(Ahi, Alo, Bhi, Blo, rowBase, colBase, (k + 1) * BK,
                       sbase + ((k + 1) & 1) * STAGE_B, tid);
            CP_COMMIT();
            CP_WAIT(1);    // stage k ready, stage k+1 in flight
        } else {
            CP_WAIT(0);
        }
        __syncthreads();

        const uint32_t st = sbase + (k & 1) * STAGE_B;
        ldsm_all(st, 0, a_row, a_uo, b_row, b_uo,
                 ahi[0], alo[0], bhi[0], blo[0]);
#pragma unroll
        for (int s = 0; s < 4; s++) {                 // four k16 steps
            const int cb = s & 1;
            if (s < 3)
                ldsm_all(st, s + 1, a_row, a_uo, b_row, b_uo,
                         ahi[cb ^ 1], alo[cb ^ 1], bhi[cb ^ 1], blo[cb ^ 1]);
#pragma unroll
            for (int i = 0; i < 4; i++) {
#pragma unroll
                for (int j = 0; j < 4; j++) {
                    const uint32_t* bh = &bhi[cb][j >> 1][(j & 1) * 2];
                    const uint32_t* bl = &blo[cb][j >> 1][(j & 1) * 2];
                    mma16816(acc[i][j], ahi[cb][i], bh);   // hi*hi
                    mma16816(acc[i][j], ahi[cb][i], bl);   // hi*lo
                    mma16816(acc[i][j], alo[cb][i], bh);   // lo*hi
                }
            }
        }
    }

    // epilogue: direct global stores + bias
#pragma unroll
    for (int i = 0; i < 4; i++) {
        int row0 = rowBase + warp_m * 64 + i * 16 + (lane >> 2);
#pragma unroll
        for (int j = 0; j < 4; j++) {
            int col = colBase + warp_n * 32 + j * 8 + (lane & 3) * 2;
            float b0 = bias[col], b1 = bias[col + 1];
            float2 v0 = make_float2(acc[i][j][0] + b0, acc[i][j][1] + b1);
            float2 v1 = make_float2(acc[i][j][2] + b0, acc[i][j][3] + b1);
            *(float2*)(C + (size_t)row0 * N + col)       = v0;
            *(float2*)(C + (size_t)(row0 + 8) * N + col) = v1;
        }
    }
}

// ======================= persistent fused LSTM ==============================
// 128 CTAs x 256 threads. Warp w of CTA c owns hidden column j = c*8+w.
// WhT rows {j, F+j, 2F+j, 3F+j} live in smem for the whole kernel (128 KB).
// c-state lives in registers (lane b of each warp holds batch b).
// Grid-wide barrier between steps via atomic counter.
__device__ __forceinline__ float sigmoidf_(float x) {
    return 1.f / (1.f + __expf(-x));
}

__global__ __launch_bounds__(256, 1)
void lstm_persist() {
    extern __shared__ float sW[];       // [8 warps][4 gates][1024]
    const int tid  = threadIdx.x;
    const int wid  = tid >> 5;
    const int lane = tid & 31;
    const int cta  = blockIdx.x;
    const int j    = cta * 8 + wid;

    // load this CTA's weight slice: 8192 float4
    for (int i = tid; i < 8192; i += 256) {
        int w   = i >> 10;          // warp slot
        int rem = i & 1023;
        int g   = rem >> 8;         // gate
        int q   = rem & 255;        // float4 index
        float4 v = *(const float4*)(g_WhT +
                     ((size_t)g * F_ + (size_t)(cta * 8 + w)) * F_ + q * 4);
        *(float4*)(sW + ((w * 4 + g) * 1024) + q * 4) = v;
    }
    __syncthreads();

    const float* sw0 = sW + (wid * 4 + 0) * 1024;
    const float* sw1 = sW + (wid * 4 + 1) * 1024;
    const float* sw2 = sW + (wid * 4 + 2) * 1024;
    const float* sw3 = sW + (wid * 4 + 3) * 1024;

    float creg = 0.f;   // cell state for (batch=lane, column=j), lanes 0-7

    for (int t = 0; t < T_; t++) {
        const float* __restrict__ hin = g_h[t & 1];
        float* __restrict__ hout      = g_h[(t + 1) & 1];

        // prefetch xW gate values for this column (lanes 0-7 = batches)
        float xg0 = 0.f, xg1 = 0.f, xg2 = 0.f, xg3 = 0.f;
        if (lane < 8) {
            size_t row = ((size_t)lane * T_ + t) * G4;
            xg0 = g_xW[row + 0 * F_ + j];
            xg1 = g_xW[row + 1 * F_ + j];
            xg2 = g_xW[row + 2 * F_ + j];
            xg3 = g_xW[row + 3 * F_ + j];
        }

        // gate dot products with packed f32x2 FMA
        uint64_t acc[4][8];
#pragma unroll
        for (int g = 0; g < 4; g++)
#pragma unroll
            for (int b = 0; b < 8; b++) acc[g][b] = 0ull;

#pragma unroll 2
        for (int p = 0; p < 8; p++) {
            int k = (p * 32 + lane) * 4;
            ulonglong2 w0 = *(const ulonglong2*)(sw0 + k);
            ulonglong2 w1 = *(const ulonglong2*)(sw1 + k);
            ulonglong2 w2 = *(const ulonglong2*)(sw2 + k);
            ulonglong2 w3 = *(const ulonglong2*)(sw3 + k);
#pragma unroll
            for (int b = 0; b < 8; b++) {
                ulonglong2 hv = *(const ulonglong2*)(hin + b * F_ + k);
                acc[0][b] = fma2(w0.x, hv.x, acc[0][b]);
                acc[0][b] = fma2(w0.y, hv.y, acc[0][b]);
                acc[1][b] = fma2(w1.x, hv.x, acc[1][b]);
                acc[1][b] = fma2(w1.y, hv.y, acc[1][b]);
                acc[2][b] = fma2(w2.x, hv.x, acc[2][b]);
                acc[2][b] = fma2(w2.y, hv.y, acc[2][b]);
                acc[3][b] = fma2(w3.x, hv.x, acc[3][b]);
                acc[3][b] = fma2(w3.y, hv.y, acc[3][b]);
            }
        }

        float a0[8], a1[8], a2[8], a3[8];
#pragma unroll
        for (int b = 0; b < 8; b++) {
            a0[b] = unpack_add(acc[0][b]);
            a1[b] = unpack_add(acc[1][b]);
            a2[b] = unpack_add(acc[2][b]);
            a3[b] = unpack_add(acc[3][b]);
        }
#pragma unroll
        for (int off = 16; off; off >>= 1) {
#pragma unroll
            for (int b = 0; b < 8; b++) {
                a0[b] += __shfl_xor_sync(0xffffffffu, a0[b], off);
                a1[b] += __shfl_xor_sync(0xffffffffu, a1[b], off);
                a2[b] += __shfl_xor_sync(0xffffffffu, a2[b], off);
                a3[b] += __shfl_xor_sync(0xffffffffu, a3[b], off);
            }
        }

        if (lane < 8) {
            float s0 = a0[0], s1 = a1[0], s2 = a2[0], s3 = a3[0];
#pragma unroll
            for (int b = 1; b < 8; b++) {
                if (lane == b) { s0 = a0[b]; s1 = a1[b]; s2 = a2[b]; s3 = a3[b]; }
            }
            float zi = s0 + xg0;
            float zf = s1 + xg1;
            float zg = s2 + xg2;
            float zo = s3 + xg3;

            float cn = sigmoidf_(zf) * creg + sigmoidf_(zi) * tanhf(zg);
            float hn = sigmoidf_(zo) * tanhf(cn);
            creg = cn;

            hout[lane * F_ + j] = hn;
            // write hs directly as hi/lo bf16 (GEMM A operand), row = b*T_+t
            size_t m = ((size_t)lane * T_ + t) * K_ + j;
            __nv_bfloat16 hb = __float2bfloat16(hn);
            g_Ahi[m] = hb;
            g_Alo[m] = __float2bfloat16(hn - __bfloat162float(hb));
        }

        // grid-wide barrier
        __threadfence();
        __syncthreads();
        if (tid == 0) {
            atomicAdd(&g_bar, 1u);
            unsigned target = (unsigned)LSTM_CTAS * (unsigned)(t + 1);
            unsigned v;
            do {
                asm volatile("ld.global.acquire.gpu.u32 %0, [%1];"
                             : "=r"(v) : "l"(&g_bar));
            } while (v < target);
        }
        __syncthreads();
    }
}

// ======================= launch =============================================
extern "C" void kernel_launch(void* const* d_in, const int* in_sizes, int n_in,
                              void* d_out, int out_size) {
    const int*   tokens = (const int*)  d_in[0];
    const float* embed  = (const float*)d_in[1];
    const float* Wx     = (const float*)d_in[2];
    const float* Wh     = (const float*)d_in[3];
    const float* bias   = (const float*)d_in[4];
    const float* Wd     = (const float*)d_in[5];
    const float* bd     = (const float*)d_in[6];
    float* out = (float*)d_out;

    float *xW = nullptr;
    __nv_bfloat16 *ahi = nullptr, *alo = nullptr;
    __nv_bfloat16 *wxh = nullptr, *wxl = nullptr, *wdh = nullptr, *wdl = nullptr;
    cudaGetSymbolAddress((void**)&xW,  g_xW);
    cudaGetSymbolAddress((void**)&ahi, g_Ahi);
    cudaGetSymbolAddress((void**)&alo, g_Alo);
    cudaGetSymbolAddress((void**)&wxh, g_WxT_hi);
    cudaGetSymbolAddress((void**)&wxl, g_WxT_lo);
    cudaGetSymbolAddress((void**)&wdh, g_WdT_hi);
    cudaGetSymbolAddress((void**)&wdl, g_WdT_lo);

    cudaFuncSetAttribute(gemm_bf16s,
                         cudaFuncAttributeMaxDynamicSharedMemorySize, GEMM_SMEM);
    cudaFuncSetAttribute(lstm_persist,
                         cudaFuncAttributeMaxDynamicSharedMemorySize, 131072);

    init_state<<<(B_ * F_ + 255) / 256, 256>>>();
    transpose_wh<<<dim3(G4 / 32, F_ / 32), dim3(32, 32)>>>(Wh);

    // ---- input path: x = embed[tokens]; xW = x @ Wx + b ----
    split_rows<<<(M_ * K_ + 255) / 256, 256>>>(embed, tokens, ahi, alo);
    transpose_split<<<dim3(G4 / 32, K_ / 32), dim3(32, 32)>>>(Wx, wxh, wxl, G4);
    gemm_bf16s<<<dim3(M_ / 128, G4 / 128), 256, GEMM_SMEM>>>(
        ahi, alo, wxh, wxl, bias, xW, G4);

    // ---- recurrence: one persistent kernel, 512 steps, grid barrier ----
    // (overwrites g_Ahi/g_Alo with hs in hi/lo bf16 form)
    lstm_persist<<<LSTM_CTAS, 256, 131072>>>();

    // ---- projection: out = hs @ Wd + bd ----
    transpose_split<<<dim3(V_ / 32, K_ / 32), dim3(32, 32)>>>(Wd, wdh, wdl, V_);
    gemm_bf16s<<<dim3(M_ / 128, V_ / 128), 256, GEMM_SMEM>>>(
        ahi, alo, wdh, wdl, bd, out, V_);
}

// round 11
// speedup vs baseline: 2.2087x; 1.1300x over previous
#include <cuda_runtime.h>
#include <cuda_bf16.h>
#include <cuda_fp16.h>
#include <math.h>
#include <stdint.h>

#define B_  8
#define T_  512
#define F_  1024
#define G4  4096           // 4*F
#define V_  32000
#define M_  (B_*T_)        // 4096 rows
#define K_  1024
#define LSTM_CTAS 128

// ---------------- scratch (device globals; no allocation allowed) ----------
__device__ float g_xW[(size_t)M_ * G4];              // 64 MB : x@Wx + b
__device__ float g_WhT[(size_t)G4 * F_];             // 16 MB : Wh^T [4F][F]
__device__ float g_h[2][B_ * F_];                    // ping-pong hidden state
__device__ unsigned g_bar;                           // grid barrier counter
// bf16 split operands (input GEMM: exact to 2^-16, feeds recurrence)
__device__ __nv_bfloat16 g_Ahi[(size_t)M_ * K_];     // 8 MB : embed rows hi
__device__ __nv_bfloat16 g_Alo[(size_t)M_ * K_];     // 8 MB : embed rows lo
__device__ __nv_bfloat16 g_WxT_hi[(size_t)G4 * K_];  // 8 MB  [4F][F]
__device__ __nv_bfloat16 g_WxT_lo[(size_t)G4 * K_];  // 8 MB
// fp16 operands (projection GEMM: 2-product split)
__device__ __half g_Ah[(size_t)M_ * K_];             // 8 MB : hs fp16
__device__ __half g_WdT_hi[(size_t)V_ * K_];         // 64 MB [V][F]
__device__ __half g_WdT_lo[(size_t)V_ * K_];         // 64 MB

// ======================= PTX helpers (sm_103-safe) ==========================
__device__ __forceinline__ uint32_t smem_u32(const void* p) {
    uint32_t a;
    asm("{ .reg .u64 t; cvta.to.shared.u64 t, %1; cvt.u32.u64 %0, t; }"
        : "=r"(a) : "l"(p));
    return a;
}
__device__ __forceinline__ void cp16(uint32_t s, const void* g) {
    asm volatile("cp.async.cg.shared.global [%0], [%1], 16;"
                 :: "r"(s), "l"(g) : "memory");
}
#define CP_COMMIT() asm volatile("cp.async.commit_group;" ::: "memory")
#define CP_WAIT(n)  asm volatile("cp.async.wait_group %0;" :: "n"(n) : "memory")

__device__ __forceinline__ void ldsm4(uint32_t* r, uint32_t addr) {
    asm volatile("ldmatrix.sync.aligned.m8n8.x4.shared.b16 {%0,%1,%2,%3}, [%4];"
                 : "=r"(r[0]), "=r"(r[1]), "=r"(r[2]), "=r"(r[3]) : "r"(addr));
}
__device__ __forceinline__ void mma_bf16(float* c, const uint32_t* a,
                                         const uint32_t* b) {
    asm volatile(
        "mma.sync.aligned.m16n8k16.row.col.f32.bf16.bf16.f32 "
        "{%0,%1,%2,%3}, {%4,%5,%6,%7}, {%8,%9}, {%0,%1,%2,%3};"
        : "+f"(c[0]), "+f"(c[1]), "+f"(c[2]), "+f"(c[3])
        : "r"(a[0]), "r"(a[1]), "r"(a[2]), "r"(a[3]), "r"(b[0]), "r"(b[1]));
}
__device__ __forceinline__ void mma_f16(float* c, const uint32_t* a,
                                        const uint32_t* b) {
    asm volatile(
        "mma.sync.aligned.m16n8k16.row.col.f32.f16.f16.f32 "
        "{%0,%1,%2,%3}, {%4,%5,%6,%7}, {%8,%9}, {%0,%1,%2,%3};"
        : "+f"(c[0]), "+f"(c[1]), "+f"(c[2]), "+f"(c[3])
        : "r"(a[0]), "r"(a[1]), "r"(a[2]), "r"(a[3]), "r"(b[0]), "r"(b[1]));
}
// packed fp32x2 FMA (sm_100+ family, not 'a'-gated)
__device__ __forceinline__ uint64_t fma2(uint64_t a, uint64_t b, uint64_t c) {
    uint64_t d;
    asm("fma.rn.f32x2 %0, %1, %2, %3;" : "=l"(d) : "l"(a), "l"(b), "l"(c));
    return d;
}
__device__ __forceinline__ float unpack_add(uint64_t a) {
    float lo, hi;
    asm("mov.b64 {%0,%1}, %2;" : "=f"(lo), "=f"(hi) : "l"(a));
    return lo + hi;
}

// ======================= prep kernels =======================================
__global__ void init_state() {
    int i = blockIdx.x * blockDim.x + threadIdx.x;
    if (i < B_ * F_) { g_h[0][i] = 0.f; g_h[1][i] = 0.f; }
    if (i == 0) g_bar = 0u;
}

__global__ void transpose_wh(const float* __restrict__ Wh) {
    __shared__ float tile[32][33];
    int n = blockIdx.x * 32 + threadIdx.x;
    int k = blockIdx.y * 32 + threadIdx.y;
    tile[threadIdx.y][threadIdx.x] = Wh[(size_t)k * G4 + n];
    __syncthreads();
    int n2 = blockIdx.x * 32 + threadIdx.y;
    int k2 = blockIdx.y * 32 + threadIdx.x;
    g_WhT[(size_t)n2 * F_ + k2] = tile[threadIdx.x][threadIdx.y];
}

// embed[tokens] fp32 -> hi/lo bf16 rows
__global__ void split_rows(const float* __restrict__ src,
                           const int* __restrict__ tokens,
                           __nv_bfloat16* __restrict__ hi,
                           __nv_bfloat16* __restrict__ lo) {
    size_t idx = (size_t)blockIdx.x * blockDim.x + threadIdx.x;
    if (idx >= (size_t)M_ * K_) return;
    size_t row = idx >> 10, col = idx & 1023;
    float x = src[(size_t)tokens[row] * K_ + col];
    __nv_bfloat16 h = __float2bfloat16(x);
    hi[idx] = h;
    lo[idx] = __float2bfloat16(x - __bfloat162float(h));
}

// W fp32 [1024 x N] -> WT hi/lo bf16 [N x 1024]   (Wx path)
__global__ void transpose_split(const float* __restrict__ W,
                                __nv_bfloat16* __restrict__ Thi,
                                __nv_bfloat16* __restrict__ Tlo, int N) {
    __shared__ float tile[32][33];
    int n  = blockIdx.x * 32 + threadIdx.x;
    int k0 = blockIdx.y * 32;
#pragma unroll
    for (int r = threadIdx.y; r < 32; r += 8)
        tile[r][threadIdx.x] = W[(size_t)(k0 + r) * N + n];
    __syncthreads();
#pragma unroll
    for (int rr = threadIdx.y; rr < 32; rr += 8) {
        int n2 = blockIdx.x * 32 + rr;
        int k2 = k0 + threadIdx.x;
        float x = tile[threadIdx.x][rr];
        __nv_bfloat16 h = __float2bfloat16(x);
        size_t o = (size_t)n2 * K_ + k2;
        Thi[o] = h;
        Tlo[o] = __float2bfloat16(x - __bfloat162float(h));
    }
}

// W fp32 [1024 x N] -> WT hi/lo fp16 [N x 1024]   (Wd path)
__global__ void transpose_split_h(const float* __restrict__ W,
                                  __half* __restrict__ Thi,
                                  __half* __restrict__ Tlo, int N) {
    __shared__ float tile[32][33];
    int n  = blockIdx.x * 32 + threadIdx.x;
    int k0 = blockIdx.y * 32;
#pragma unroll
    for (int r = threadIdx.y; r < 32; r += 8)
        tile[r][threadIdx.x] = W[(size_t)(k0 + r) * N + n];
    __syncthreads();
#pragma unroll
    for (int rr = threadIdx.y; rr < 32; rr += 8) {
        int n2 = blockIdx.x * 32 + rr;
        int k2 = k0 + threadIdx.x;
        float x = tile[threadIdx.x][rr];
        __half h = __float2half_rn(x);
        size_t o = (size_t)n2 * K_ + k2;
        Thi[o] = h;
        Tlo[o] = __float2half_rn(x - __half2float(h));
    }
}

// ======================= common GEMM plumbing ===============================
#define BK      64
#define NCHUNK  (K_ / BK)          // 16
#define TILE_B  (128 * 128)        // 16 KB: 128 rows x 64 halfwords (128B/row)

// swizzled byte offset within one tile for (row, 16B-unit u in 0..7)
__device__ __forceinline__ uint32_t sw_off(int r, int u) {
    return (uint32_t)(r * 128 + ((u ^ (r & 7)) << 4));
}

// ======================= 3-product bf16 GEMM (input path) ===================
#define STAGE3_B (4 * TILE_B)            // 64 KB
#define GEMM3_SMEM (2 * STAGE3_B)        // 128 KB

__device__ __forceinline__ void load_stage3(const __nv_bfloat16* __restrict__ Ahi,
                                            const __nv_bfloat16* __restrict__ Alo,
                                            const __nv_bfloat16* __restrict__ Bhi,
                                            const __nv_bfloat16* __restrict__ Blo,
                                            int rowBase, int colBase, int k0,
                                            uint32_t stage, int tid) {
#pragma unroll
    for (int i = 0; i < 4; i++) {
        int e = tid + i * 256;
        int r = e >> 3, u = e & 7;
        uint32_t so = sw_off(r, u);
        size_t goA = (size_t)(rowBase + r) * K_ + k0 + u * 8;
        size_t goB = (size_t)(colBase + r) * K_ + k0 + u * 8;
        cp16(stage + 0 * TILE_B + so, Ahi + goA);
        cp16(stage + 1 * TILE_B + so, Alo + goA);
        cp16(stage + 2 * TILE_B + so, Bhi + goB);
        cp16(stage + 3 * TILE_B + so, Blo + goB);
    }
}

__device__ __forceinline__ void ldsm_abx2(uint32_t st, int s,
                                          int a_row, int a_uo,
                                          int b_row, int b_uo,
                                          uint32_t (*a0)[4], uint32_t (*a1)[4],
                                          uint32_t (*b0)[4], uint32_t (*b1)[4],
                                          uint32_t aoff0, uint32_t aoff1,
                                          uint32_t boff0, uint32_t boff1) {
#pragma unroll
    for (int i = 0; i < 4; i++) {
        int r = a_row + i * 16;
        uint32_t off = sw_off(r, 2 * s + a_uo);
        ldsm4(a0[i], st + aoff0 + off);
        if (a1) ldsm4(a1[i], st + aoff1 + off);
    }
#pragma unroll
    for (int p = 0; p < 2; p++) {
        int r = b_row + p * 16;
        uint32_t off = sw_off(r, 2 * s + b_uo);
        ldsm4(b0[p], st + boff0 + off);
        ldsm4(b1[p], st + boff1 + off);
    }
}

__global__ __launch_bounds__(256, 1)
void gemm_bf16s(const __nv_bfloat16* __restrict__ Ahi,
                const __nv_bfloat16* __restrict__ Alo,
                const __nv_bfloat16* __restrict__ Bhi,
                const __nv_bfloat16* __restrict__ Blo,
                const float* __restrict__ bias,
                float* __restrict__ C, int N)
{
    extern __shared__ char smem[];
    const uint32_t sbase = smem_u32(smem);
    const int tid  = threadIdx.x;
    const int wid  = tid >> 5;
    const int lane = tid & 31;
    const int warp_m = wid & 1;
    const int warp_n = wid >> 1;
    const int rowBase = blockIdx.x * 128;
    const int colBase = blockIdx.y * 128;

    float acc[4][4][4];
#pragma unroll
    for (int i = 0; i < 4; i++)
#pragma unroll
        for (int j = 0; j < 4; j++)
#pragma unroll
            for (int q = 0; q < 4; q++) acc[i][j][q] = 0.f;

    const int a_row = warp_m * 64 + (lane & 15);
    const int a_uo  = lane >> 4;
    const int b_row = warp_n * 32 + ((lane >> 4) << 3) + (lane & 7);
    const int b_uo  = (lane >> 3) & 1;

    uint32_t ahi[2][4][4], alo[2][4][4], bhi[2][2][4], blo[2][2][4];

    load_stage3(Ahi, Alo, Bhi, Blo, rowBase, colBase, 0, sbase, tid);
    CP_COMMIT();

    for (int k = 0; k < NCHUNK; k++) {
        __syncthreads();
        if (k + 1 < NCHUNK) {
            load_stage3(Ahi, Alo, Bhi, Blo, rowBase, colBase, (k + 1) * BK,
                        sbase + ((k + 1) & 1) * STAGE3_B, tid);
            CP_COMMIT();
            CP_WAIT(1);
        } else {
            CP_WAIT(0);
        }
        __syncthreads();

        const uint32_t st = sbase + (k & 1) * STAGE3_B;
        ldsm_abx2(st, 0, a_row, a_uo, b_row, b_uo,
                  ahi[0], alo[0], bhi[0], blo[0],
                  0, TILE_B, 2 * TILE_B, 3 * TILE_B);
#pragma unroll
        for (int s = 0; s < 4; s++) {
            const int cb = s & 1;
            if (s < 3)
                ldsm_abx2(st, s + 1, a_row, a_uo, b_row, b_uo,
                          ahi[cb ^ 1], alo[cb ^ 1], bhi[cb ^ 1], blo[cb ^ 1],
                          0, TILE_B, 2 * TILE_B, 3 * TILE_B);
#pragma unroll
            for (int i = 0; i < 4; i++) {
#pragma unroll
                for (int j = 0; j < 4; j++) {
                    const uint32_t* bh = &bhi[cb][j >> 1][(j & 1) * 2];
                    const uint32_t* bl = &blo[cb][j >> 1][(j & 1) * 2];
                    mma_bf16(acc[i][j], ahi[cb][i], bh);
                    mma_bf16(acc[i][j], ahi[cb][i], bl);
                    mma_bf16(acc[i][j], alo[cb][i], bh);
                }
            }
        }
    }

#pragma unroll
    for (int i = 0; i < 4; i++) {
        int row0 = rowBase + warp_m * 64 + i * 16 + (lane >> 2);
#pragma unroll
        for (int j = 0; j < 4; j++) {
            int col = colBase + warp_n * 32 + j * 8 + (lane & 3) * 2;
            float b0 = bias[col], b1 = bias[col + 1];
            float2 v0 = make_float2(acc[i][j][0] + b0, acc[i][j][1] + b1);
            float2 v1 = make_float2(acc[i][j][2] + b0, acc[i][j][3] + b1);
            *(float2*)(C + (size_t)row0 * N + col)       = v0;
            *(float2*)(C + (size_t)(row0 + 8) * N + col) = v1;
        }
    }
}

// ======================= 2-product fp16 GEMM (projection) ===================
// C = Ah @ (Bhi + Blo)^T + bias.  Ah single fp16, B split fp16 hi/lo.
#define STAGE2_B (3 * TILE_B)            // 48 KB
#define GEMM2_SMEM (2 * STAGE2_B)        // 96 KB

__device__ __forceinline__ void load_stage2(const __half* __restrict__ Ah,
                                            const __half* __restrict__ Bhi,
                                            const __half* __restrict__ Blo,
                                            int rowBase, int colBase, int k0,
                                            uint32_t stage, int tid) {
#pragma unroll
    for (int i = 0; i < 4; i++) {
        int e = tid + i * 256;
        int r = e >> 3, u = e & 7;
        uint32_t so = sw_off(r, u);
        size_t goA = (size_t)(rowBase + r) * K_ + k0 + u * 8;
        size_t goB = (size_t)(colBase + r) * K_ + k0 + u * 8;
        cp16(stage + 0 * TILE_B + so, Ah  + goA);
        cp16(stage + 1 * TILE_B + so, Bhi + goB);
        cp16(stage + 2 * TILE_B + so, Blo + goB);
    }
}

__global__ __launch_bounds__(256, 1)
void gemm_f16_2(const __half* __restrict__ Ah,
                const __half* __restrict__ Bhi,
                const __half* __restrict__ Blo,
                const float* __restrict__ bias,
                float* __restrict__ C, int N)
{
    extern __shared__ char smem[];
    const uint32_t sbase = smem_u32(smem);
    const int tid  = threadIdx.x;
    const int wid  = tid >> 5;
    const int lane = tid & 31;
    const int warp_m = wid & 1;
    const int warp_n = wid >> 1;
    const int rowBase = blockIdx.x * 128;
    const int colBase = blockIdx.y * 128;

    float acc[4][4][4];
#pragma unroll
    for (int i = 0; i < 4; i++)
#pragma unroll
        for (int j = 0; j < 4; j++)
#pragma unroll
            for (int q = 0; q < 4; q++) acc[i][j][q] = 0.f;

    const int a_row = warp_m * 64 + (lane & 15);
    const int a_uo  = lane >> 4;
    const int b_row = warp_n * 32 + ((lane >> 4) << 3) + (lane & 7);
    const int b_uo  = (lane >> 3) & 1;

    uint32_t ah[2][4][4], bhi[2][2][4], blo[2][2][4];

    load_stage2(Ah, Bhi, Blo, rowBase, colBase, 0, sbase, tid);
    CP_COMMIT();

    for (int k = 0; k < NCHUNK; k++) {
        __syncthreads();
        if (k + 1 < NCHUNK) {
            load_stage2(Ah, Bhi, Blo, rowBase, colBase, (k + 1) * BK,
                        sbase + ((k + 1) & 1) * STAGE2_B, tid);
            CP_COMMIT();
            CP_WAIT(1);
        } else {
            CP_WAIT(0);
        }
        __syncthreads();

        const uint32_t st = sbase + (k & 1) * STAGE2_B;
        ldsm_abx2(st, 0, a_row, a_uo, b_row, b_uo,
                  ah[0], (uint32_t(*)[4])nullptr, bhi[0], blo[0],
                  0, 0, TILE_B, 2 * TILE_B);
#pragma unroll
        for (int s = 0; s < 4; s++) {
            const int cb = s & 1;
            if (s < 3)
                ldsm_abx2(st, s + 1, a_row, a_uo, b_row, b_uo,
                          ah[cb ^ 1], (uint32_t(*)[4])nullptr,
                          bhi[cb ^ 1], blo[cb ^ 1],
                          0, 0, TILE_B, 2 * TILE_B);
#pragma unroll
            for (int i = 0; i < 4; i++) {
#pragma unroll
                for (int j = 0; j < 4; j++) {
                    const uint32_t* bh = &bhi[cb][j >> 1][(j & 1) * 2];
                    const uint32_t* bl = &blo[cb][j >> 1][(j & 1) * 2];
                    mma_f16(acc[i][j], ah[cb][i], bh);
                    mma_f16(acc[i][j], ah[cb][i], bl);
                }
            }
        }
    }

#pragma unroll
    for (int i = 0; i < 4; i++) {
        int row0 = rowBase + warp_m * 64 + i * 16 + (lane >> 2);
#pragma unroll
        for (int j = 0; j < 4; j++) {
            int col = colBase + warp_n * 32 + j * 8 + (lane & 3) * 2;
            float b0 = bias[col], b1 = bias[col + 1];
            float2 v0 = make_float2(acc[i][j][0] + b0, acc[i][j][1] + b1);
            float2 v1 = make_float2(acc[i][j][2] + b0, acc[i][j][3] + b1);
            *(float2*)(C + (size_t)row0 * N + col)       = v0;
            *(float2*)(C + (size_t)(row0 + 8) * N + col) = v1;
        }
    }
}

// ======================= persistent fused LSTM ==============================
__device__ __forceinline__ float sigmoidf_(float x) {
    return 1.f / (1.f + __expf(-x));
}

__global__ __launch_bounds__(256, 1)
void lstm_persist() {
    extern __shared__ float sW[];       // [8 warps][4 gates][1024]
    const int tid  = threadIdx.x;
    const int wid  = tid >> 5;
    const int lane = tid & 31;
    const int cta  = blockIdx.x;
    const int j    = cta * 8 + wid;

    for (int i = tid; i < 8192; i += 256) {
        int w   = i >> 10;
        int rem = i & 1023;
        int g   = rem >> 8;
        int q   = rem & 255;
        float4 v = *(const float4*)(g_WhT +
                     ((size_t)g * F_ + (size_t)(cta * 8 + w)) * F_ + q * 4);
        *(float4*)(sW + ((w * 4 + g) * 1024) + q * 4) = v;
    }
    __syncthreads();

    const float* sw0 = sW + (wid * 4 + 0) * 1024;
    const float* sw1 = sW + (wid * 4 + 1) * 1024;
    const float* sw2 = sW + (wid * 4 + 2) * 1024;
    const float* sw3 = sW + (wid * 4 + 3) * 1024;

    float creg = 0.f;

    for (int t = 0; t < T_; t++) {
        const float* __restrict__ hin = g_h[t & 1];
        float* __restrict__ hout      = g_h[(t + 1) & 1];

        float xg0 = 0.f, xg1 = 0.f, xg2 = 0.f, xg3 = 0.f;
        if (lane < 8) {
            size_t row = ((size_t)lane * T_ + t) * G4;
            xg0 = g_xW[row + 0 * F_ + j];
            xg1 = g_xW[row + 1 * F_ + j];
            xg2 = g_xW[row + 2 * F_ + j];
            xg3 = g_xW[row + 3 * F_ + j];
        }

        uint64_t acc[4][8];
#pragma unroll
        for (int g = 0; g < 4; g++)
#pragma unroll
            for (int b = 0; b < 8; b++) acc[g][b] = 0ull;

#pragma unroll 2
        for (int p = 0; p < 8; p++) {
            int k = (p * 32 + lane) * 4;
            ulonglong2 w0 = *(const ulonglong2*)(sw0 + k);
            ulonglong2 w1 = *(const ulonglong2*)(sw1 + k);
            ulonglong2 w2 = *(const ulonglong2*)(sw2 + k);
            ulonglong2 w3 = *(const ulonglong2*)(sw3 + k);
#pragma unroll
            for (int b = 0; b < 8; b++) {
                ulonglong2 hv = *(const ulonglong2*)(hin + b * F_ + k);
                acc[0][b] = fma2(w0.x, hv.x, acc[0][b]);
                acc[0][b] = fma2(w0.y, hv.y, acc[0][b]);
                acc[1][b] = fma2(w1.x, hv.x, acc[1][b]);
                acc[1][b] = fma2(w1.y, hv.y, acc[1][b]);
                acc[2][b] = fma2(w2.x, hv.x, acc[2][b]);
                acc[2][b] = fma2(w2.y, hv.y, acc[2][b]);
                acc[3][b] = fma2(w3.x, hv.x, acc[3][b]);
                acc[3][b] = fma2(w3.y, hv.y, acc[3][b]);
            }
        }

        float a0[8], a1[8], a2[8], a3[8];
#pragma unroll
        for (int b = 0; b < 8; b++) {
            a0[b] = unpack_add(acc[0][b]);
            a1[b] = unpack_add(acc[1][b]);
            a2[b] = unpack_add(acc[2][b]);
            a3[b] = unpack_add(acc[3][b]);
        }
#pragma unroll
        for (int off = 16; off; off >>= 1) {
#pragma unroll
            for (int b = 0; b < 8; b++) {
                a0[b] += __shfl_xor_sync(0xffffffffu, a0[b], off);
                a1[b] += __shfl_xor_sync(0xffffffffu, a1[b], off);
                a2[b] += __shfl_xor_sync(0xffffffffu, a2[b], off);
                a3[b] += __shfl_xor_sync(0xffffffffu, a3[b], off);
            }
        }

        if (lane < 8) {
            float s0 = a0[0], s1 = a1[0], s2 = a2[0], s3 = a3[0];
#pragma unroll
            for (int b = 1; b < 8; b++) {
                if (lane == b) { s0 = a0[b]; s1 = a1[b]; s2 = a2[b]; s3 = a3[b]; }
            }
            float zi = s0 + xg0;
            float zf = s1 + xg1;
            float zg = s2 + xg2;
            float zo = s3 + xg3;

            float cn = sigmoidf_(zf) * creg + sigmoidf_(zi) * tanhf(zg);
            float hn = sigmoidf_(zo) * tanhf(cn);
            creg = cn;

            hout[lane * F_ + j] = hn;
            // hs as single fp16 for the projection GEMM
            g_Ah[((size_t)lane * T_ + t) * K_ + j] = __float2half_rn(hn);
        }

        __threadfence();
        __syncthreads();
        if (tid == 0) {
            atomicAdd(&g_bar, 1u);
            unsigned target = (unsigned)LSTM_CTAS * (unsigned)(t + 1);
            unsigned v;
            do {
                asm volatile("ld.global.acquire.gpu.u32 %0, [%1];"
                             : "=r"(v) : "l"(&g_bar));
            } while (v < target);
        }
        __syncthreads();
    }
}

// ======================= launch =============================================
extern "C" void kernel_launch(void* const* d_in, const int* in_sizes, int n_in,
                              void* d_out, int out_size) {
    const int*   tokens = (const int*)  d_in[0];
    const float* embed  = (const float*)d_in[1];
    const float* Wx     = (const float*)d_in[2];
    const float* Wh     = (const float*)d_in[3];
    const float* bias   = (const float*)d_in[4];
    const float* Wd     = (const float*)d_in[5];
    const float* bd     = (const float*)d_in[6];
    float* out = (float*)d_out;

    float *xW = nullptr;
    __nv_bfloat16 *ahi = nullptr, *alo = nullptr, *wxh = nullptr, *wxl = nullptr;
    __half *ah = nullptr, *wdh = nullptr, *wdl = nullptr;
    cudaGetSymbolAddress((void**)&xW,  g_xW);
    cudaGetSymbolAddress((void**)&ahi, g_Ahi);
    cudaGetSymbolAddress((void**)&alo, g_Alo);
    cudaGetSymbolAddress((void**)&wxh, g_WxT_hi);
    cudaGetSymbolAddress((void**)&wxl, g_WxT_lo);
    cudaGetSymbolAddress((void**)&ah,  g_Ah);
    cudaGetSymbolAddress((void**)&wdh, g_WdT_hi);
    cudaGetSymbolAddress((void**)&wdl, g_WdT_lo);

    cudaFuncSetAttribute(gemm_bf16s,
                         cudaFuncAttributeMaxDynamicSharedMemorySize, GEMM3_SMEM);
    cudaFuncSetAttribute(gemm_f16_2,
                         cudaFuncAttributeMaxDynamicSharedMemorySize, GEMM2_SMEM);
    cudaFuncSetAttribute(lstm_persist,
                         cudaFuncAttributeMaxDynamicSharedMemorySize, 131072);

    init_state<<<(B_ * F_ + 255) / 256, 256>>>();
    transpose_wh<<<dim3(G4 / 32, F_ / 32), dim3(32, 32)>>>(Wh);

    // ---- input path: x = embed[tokens]; xW = x @ Wx + b (bf16 3-product) ----
    split_rows<<<(M_ * K_ + 255) / 256, 256>>>(embed, tokens, ahi, alo);
    transpose_split<<<dim3(G4 / 32, K_ / 32), dim3(32, 8)>>>(Wx, wxh, wxl, G4);
    gemm_bf16s<<<dim3(M_ / 128, G4 / 128), 256, GEMM3_SMEM>>>(
        ahi, alo, wxh, wxl, bias, xW, G4);

    // ---- recurrence: persistent kernel, writes hs as fp16 into g_Ah ----
    lstm_persist<<<LSTM_CTAS, 256, 131072>>>();

    // ---- projection: out = hs @ Wd + bd (fp16 2-product) ----
    transpose_split_h<<<dim3(V_ / 32, K_ / 32), dim3(32, 8)>>>(Wd, wdh, wdl, V_);
    gemm_f16_2<<<dim3(M_ / 128, V_ / 128), 256, GEMM2_SMEM>>>(
        ah, wdh, wdl, bd, out, V_);
}

// round 12
// speedup vs baseline: 2.6851x; 1.2157x over previous
#include <cuda_runtime.h>
#include <cuda_bf16.h>
#include <cuda_fp16.h>
#include <math.h>
#include <stdint.h>

#define B_  8
#define T_  512
#define F_  1024
#define G4  4096           // 4*F
#define V_  32000
#define M_  (B_*T_)        // 4096 rows
#define K_  1024
#define LSTM_CTAS 128

// ---------------- scratch (device globals; no allocation allowed) ----------
__device__ float g_xW[(size_t)M_ * G4];              // 64 MB : x@Wx + b
__device__ float g_WhT[(size_t)G4 * F_];             // 16 MB : Wh^T [4F][F]
__device__ float g_h[2][B_ * F_];                    // ping-pong hidden state
__device__ unsigned g_bar;                           // grid barrier counter
// bf16 split operands (input GEMM: exact to 2^-16, feeds recurrence)
__device__ __nv_bfloat16 g_Ahi[(size_t)M_ * K_];     // 8 MB : embed rows hi
__device__ __nv_bfloat16 g_Alo[(size_t)M_ * K_];     // 8 MB : embed rows lo
__device__ __nv_bfloat16 g_WxT_hi[(size_t)G4 * K_];  // 8 MB  [4F][F]
__device__ __nv_bfloat16 g_WxT_lo[(size_t)G4 * K_];  // 8 MB
// fp16 operands (projection GEMM: single product, calibrated err ~3e-4)
__device__ __half g_Ah[(size_t)M_ * K_];             // 8 MB : hs fp16
__device__ __half g_WdT[(size_t)V_ * K_];            // 64 MB [V][F] fp16

// ======================= PTX helpers (sm_103-safe) ==========================
__device__ __forceinline__ uint32_t smem_u32(const void* p) {
    uint32_t a;
    asm("{ .reg .u64 t; cvta.to.shared.u64 t, %1; cvt.u32.u64 %0, t; }"
        : "=r"(a) : "l"(p));
    return a;
}
__device__ __forceinline__ void cp16(uint32_t s, const void* g) {
    asm volatile("cp.async.cg.shared.global [%0], [%1], 16;"
                 :: "r"(s), "l"(g) : "memory");
}
#define CP_COMMIT() asm volatile("cp.async.commit_group;" ::: "memory")
#define CP_WAIT(n)  asm volatile("cp.async.wait_group %0;" :: "n"(n) : "memory")

__device__ __forceinline__ void ldsm4(uint32_t* r, uint32_t addr) {
    asm volatile("ldmatrix.sync.aligned.m8n8.x4.shared.b16 {%0,%1,%2,%3}, [%4];"
                 : "=r"(r[0]), "=r"(r[1]), "=r"(r[2]), "=r"(r[3]) : "r"(addr));
}
__device__ __forceinline__ void mma_bf16(float* c, const uint32_t* a,
                                         const uint32_t* b) {
    asm volatile(
        "mma.sync.aligned.m16n8k16.row.col.f32.bf16.bf16.f32 "
        "{%0,%1,%2,%3}, {%4,%5,%6,%7}, {%8,%9}, {%0,%1,%2,%3};"
        : "+f"(c[0]), "+f"(c[1]), "+f"(c[2]), "+f"(c[3])
        : "r"(a[0]), "r"(a[1]), "r"(a[2]), "r"(a[3]), "r"(b[0]), "r"(b[1]));
}
__device__ __forceinline__ void mma_f16(float* c, const uint32_t* a,
                                        const uint32_t* b) {
    asm volatile(
        "mma.sync.aligned.m16n8k16.row.col.f32.f16.f16.f32 "
        "{%0,%1,%2,%3}, {%4,%5,%6,%7}, {%8,%9}, {%0,%1,%2,%3};"
        : "+f"(c[0]), "+f"(c[1]), "+f"(c[2]), "+f"(c[3])
        : "r"(a[0]), "r"(a[1]), "r"(a[2]), "r"(a[3]), "r"(b[0]), "r"(b[1]));
}
// packed fp32x2 FMA (sm_100+ family, not 'a'-gated)
__device__ __forceinline__ uint64_t fma2(uint64_t a, uint64_t b, uint64_t c) {
    uint64_t d;
    asm("fma.rn.f32x2 %0, %1, %2, %3;" : "=l"(d) : "l"(a), "l"(b), "l"(c));
    return d;
}
__device__ __forceinline__ float unpack_add(uint64_t a) {
    float lo, hi;
    asm("mov.b64 {%0,%1}, %2;" : "=f"(lo), "=f"(hi) : "l"(a));
    return lo + hi;
}

// ======================= prep kernels =======================================
__global__ void init_state() {
    int i = blockIdx.x * blockDim.x + threadIdx.x;
    if (i < B_ * F_) { g_h[0][i] = 0.f; g_h[1][i] = 0.f; }
    if (i == 0) g_bar = 0u;
}

__global__ void transpose_wh(const float* __restrict__ Wh) {
    __shared__ float tile[32][33];
    int n = blockIdx.x * 32 + threadIdx.x;
    int k = blockIdx.y * 32 + threadIdx.y;
    tile[threadIdx.y][threadIdx.x] = Wh[(size_t)k * G4 + n];
    __syncthreads();
    int n2 = blockIdx.x * 32 + threadIdx.y;
    int k2 = blockIdx.y * 32 + threadIdx.x;
    g_WhT[(size_t)n2 * F_ + k2] = tile[threadIdx.x][threadIdx.y];
}

// embed[tokens] fp32 -> hi/lo bf16 rows
__global__ void split_rows(const float* __restrict__ src,
                           const int* __restrict__ tokens,
                           __nv_bfloat16* __restrict__ hi,
                           __nv_bfloat16* __restrict__ lo) {
    size_t idx = (size_t)blockIdx.x * blockDim.x + threadIdx.x;
    if (idx >= (size_t)M_ * K_) return;
    size_t row = idx >> 10, col = idx & 1023;
    float x = src[(size_t)tokens[row] * K_ + col];
    __nv_bfloat16 h = __float2bfloat16(x);
    hi[idx] = h;
    lo[idx] = __float2bfloat16(x - __bfloat162float(h));
}

// W fp32 [1024 x N] -> WT hi/lo bf16 [N x 1024]   (Wx path)
__global__ void transpose_split(const float* __restrict__ W,
                                __nv_bfloat16* __restrict__ Thi,
                                __nv_bfloat16* __restrict__ Tlo, int N) {
    __shared__ float tile[32][33];
    int n  = blockIdx.x * 32 + threadIdx.x;
    int k0 = blockIdx.y * 32;
#pragma unroll
    for (int r = threadIdx.y; r < 32; r += 8)
        tile[r][threadIdx.x] = W[(size_t)(k0 + r) * N + n];
    __syncthreads();
#pragma unroll
    for (int rr = threadIdx.y; rr < 32; rr += 8) {
        int n2 = blockIdx.x * 32 + rr;
        int k2 = k0 + threadIdx.x;
        float x = tile[threadIdx.x][rr];
        __nv_bfloat16 h = __float2bfloat16(x);
        size_t o = (size_t)n2 * K_ + k2;
        Thi[o] = h;
        Tlo[o] = __float2bfloat16(x - __bfloat162float(h));
    }
}

// W fp32 [1024 x N] -> WT single fp16 [N x 1024]   (Wd path)
__global__ void transpose_h(const float* __restrict__ W,
                            __half* __restrict__ Th, int N) {
    __shared__ float tile[32][33];
    int n  = blockIdx.x * 32 + threadIdx.x;
    int k0 = blockIdx.y * 32;
#pragma unroll
    for (int r = threadIdx.y; r < 32; r += 8)
        tile[r][threadIdx.x] = W[(size_t)(k0 + r) * N + n];
    __syncthreads();
#pragma unroll
    for (int rr = threadIdx.y; rr < 32; rr += 8) {
        int n2 = blockIdx.x * 32 + rr;
        int k2 = k0 + threadIdx.x;
        Th[(size_t)n2 * K_ + k2] = __float2half_rn(tile[threadIdx.x][rr]);
    }
}

// ======================= common GEMM plumbing ===============================
#define BK      64
#define NCHUNK  (K_ / BK)          // 16
#define TILE_B  (128 * 128)        // 16 KB: 128 rows x 64 halfwords (128B/row)

// swizzled byte offset within one tile for (row, 16B-unit u in 0..7)
__device__ __forceinline__ uint32_t sw_off(int r, int u) {
    return (uint32_t)(r * 128 + ((u ^ (r & 7)) << 4));
}

// ======================= 3-product bf16 GEMM (input path) ===================
#define STAGE3_B (4 * TILE_B)            // 64 KB
#define GEMM3_SMEM (2 * STAGE3_B)        // 128 KB

__device__ __forceinline__ void load_stage3(const __nv_bfloat16* __restrict__ Ahi,
                                            const __nv_bfloat16* __restrict__ Alo,
                                            const __nv_bfloat16* __restrict__ Bhi,
                                            const __nv_bfloat16* __restrict__ Blo,
                                            int rowBase, int colBase, int k0,
                                            uint32_t stage, int tid) {
#pragma unroll
    for (int i = 0; i < 4; i++) {
        int e = tid + i * 256;
        int r = e >> 3, u = e & 7;
        uint32_t so = sw_off(r, u);
        size_t goA = (size_t)(rowBase + r) * K_ + k0 + u * 8;
        size_t goB = (size_t)(colBase + r) * K_ + k0 + u * 8;
        cp16(stage + 0 * TILE_B + so, Ahi + goA);
        cp16(stage + 1 * TILE_B + so, Alo + goA);
        cp16(stage + 2 * TILE_B + so, Bhi + goB);
        cp16(stage + 3 * TILE_B + so, Blo + goB);
    }
}

__global__ __launch_bounds__(256, 1)
void gemm_bf16s(const __nv_bfloat16* __restrict__ Ahi,
                const __nv_bfloat16* __restrict__ Alo,
                const __nv_bfloat16* __restrict__ Bhi,
                const __nv_bfloat16* __restrict__ Blo,
                const float* __restrict__ bias,
                float* __restrict__ C, int N)
{
    extern __shared__ char smem[];
    const uint32_t sbase = smem_u32(smem);
    const int tid  = threadIdx.x;
    const int wid  = tid >> 5;
    const int lane = tid & 31;
    const int warp_m = wid & 1;
    const int warp_n = wid >> 1;
    const int rowBase = blockIdx.x * 128;
    const int colBase = blockIdx.y * 128;

    float acc[4][4][4];
#pragma unroll
    for (int i = 0; i < 4; i++)
#pragma unroll
        for (int j = 0; j < 4; j++)
#pragma unroll
            for (int q = 0; q < 4; q++) acc[i][j][q] = 0.f;

    const int a_row = warp_m * 64 + (lane & 15);
    const int a_uo  = lane >> 4;
    const int b_row = warp_n * 32 + ((lane >> 4) << 3) + (lane & 7);
    const int b_uo  = (lane >> 3) & 1;

    uint32_t ahi[2][4][4], alo[2][4][4], bhi[2][2][4], blo[2][2][4];

    load_stage3(Ahi, Alo, Bhi, Blo, rowBase, colBase, 0, sbase, tid);
    CP_COMMIT();

    for (int k = 0; k < NCHUNK; k++) {
        __syncthreads();
        if (k + 1 < NCHUNK) {
            load_stage3(Ahi, Alo, Bhi, Blo, rowBase, colBase, (k + 1) * BK,
                        sbase + ((k + 1) & 1) * STAGE3_B, tid);
            CP_COMMIT();
            CP_WAIT(1);
        } else {
            CP_WAIT(0);
        }
        __syncthreads();

        const uint32_t st = sbase + (k & 1) * STAGE3_B;
#pragma unroll
        for (int pre = 0; pre < 1; pre++) {   // fill buffer 0
#pragma unroll
            for (int i = 0; i < 4; i++) {
                uint32_t off = sw_off(a_row + i * 16, a_uo);
                ldsm4(ahi[0][i], st + off);
                ldsm4(alo[0][i], st + TILE_B + off);
            }
#pragma unroll
            for (int p = 0; p < 2; p++) {
                uint32_t off = sw_off(b_row + p * 16, b_uo);
                ldsm4(bhi[0][p], st + 2 * TILE_B + off);
                ldsm4(blo[0][p], st + 3 * TILE_B + off);
            }
        }
#pragma unroll
        for (int s = 0; s < 4; s++) {
            const int cb = s & 1;
            if (s < 3) {
#pragma unroll
                for (int i = 0; i < 4; i++) {
                    uint32_t off = sw_off(a_row + i * 16, 2 * (s + 1) + a_uo);
                    ldsm4(ahi[cb ^ 1][i], st + off);
                    ldsm4(alo[cb ^ 1][i], st + TILE_B + off);
                }
#pragma unroll
                for (int p = 0; p < 2; p++) {
                    uint32_t off = sw_off(b_row + p * 16, 2 * (s + 1) + b_uo);
                    ldsm4(bhi[cb ^ 1][p], st + 2 * TILE_B + off);
                    ldsm4(blo[cb ^ 1][p], st + 3 * TILE_B + off);
                }
            }
#pragma unroll
            for (int i = 0; i < 4; i++) {
#pragma unroll
                for (int j = 0; j < 4; j++) {
                    const uint32_t* bh = &bhi[cb][j >> 1][(j & 1) * 2];
                    const uint32_t* bl = &blo[cb][j >> 1][(j & 1) * 2];
                    mma_bf16(acc[i][j], ahi[cb][i], bh);
                    mma_bf16(acc[i][j], ahi[cb][i], bl);
                    mma_bf16(acc[i][j], alo[cb][i], bh);
                }
            }
        }
    }

#pragma unroll
    for (int i = 0; i < 4; i++) {
        int row0 = rowBase + warp_m * 64 + i * 16 + (lane >> 2);
#pragma unroll
        for (int j = 0; j < 4; j++) {
            int col = colBase + warp_n * 32 + j * 8 + (lane & 3) * 2;
            float b0 = bias[col], b1 = bias[col + 1];
            float2 v0 = make_float2(acc[i][j][0] + b0, acc[i][j][1] + b1);
            float2 v1 = make_float2(acc[i][j][2] + b0, acc[i][j][3] + b1);
            *(float2*)(C + (size_t)row0 * N + col)       = v0;
            *(float2*)(C + (size_t)(row0 + 8) * N + col) = v1;
        }
    }
}

// ======================= 1-product fp16 GEMM (projection) ===================
// C = Ah @ Bh^T + bias, both operands single fp16 (calibrated rel_err ~3e-4).
#define STAGE1_B (2 * TILE_B)            // 32 KB
#define GEMM1_SMEM (2 * STAGE1_B)        // 64 KB

__device__ __forceinline__ void load_stage1(const __half* __restrict__ Ah,
                                            const __half* __restrict__ Bh,
                                            int rowBase, int colBase, int k0,
                                            uint32_t stage, int tid) {
#pragma unroll
    for (int i = 0; i < 4; i++) {
        int e = tid + i * 256;
        int r = e >> 3, u = e & 7;
        uint32_t so = sw_off(r, u);
        cp16(stage + so,          Ah + (size_t)(rowBase + r) * K_ + k0 + u * 8);
        cp16(stage + TILE_B + so, Bh + (size_t)(colBase + r) * K_ + k0 + u * 8);
    }
}

__global__ __launch_bounds__(256, 1)
void gemm_f16_1(const __half* __restrict__ Ah,
                const __half* __restrict__ Bh,
                const float* __restrict__ bias,
                float* __restrict__ C, int N)
{
    extern __shared__ char smem[];
    const uint32_t sbase = smem_u32(smem);
    const int tid  = threadIdx.x;
    const int wid  = tid >> 5;
    const int lane = tid & 31;
    const int warp_m = wid & 1;
    const int warp_n = wid >> 1;
    const int rowBase = blockIdx.x * 128;   // m fastest -> B-tile reuse in L2
    const int colBase = blockIdx.y * 128;

    float acc[4][4][4];
#pragma unroll
    for (int i = 0; i < 4; i++)
#pragma unroll
        for (int j = 0; j < 4; j++)
#pragma unroll
            for (int q = 0; q < 4; q++) acc[i][j][q] = 0.f;

    const int a_row = warp_m * 64 + (lane & 15);
    const int a_uo  = lane >> 4;
    const int b_row = warp_n * 32 + ((lane >> 4) << 3) + (lane & 7);
    const int b_uo  = (lane >> 3) & 1;

    uint32_t ah[2][4][4], bh[2][2][4];

    load_stage1(Ah, Bh, rowBase, colBase, 0, sbase, tid);
    CP_COMMIT();

    for (int k = 0; k < NCHUNK; k++) {
        __syncthreads();
        if (k + 1 < NCHUNK) {
            load_stage1(Ah, Bh, rowBase, colBase, (k + 1) * BK,
                        sbase + ((k + 1) & 1) * STAGE1_B, tid);
            CP_COMMIT();
            CP_WAIT(1);
        } else {
            CP_WAIT(0);
        }
        __syncthreads();

        const uint32_t st = sbase + (k & 1) * STAGE1_B;
#pragma unroll
        for (int i = 0; i < 4; i++)
            ldsm4(ah[0][i], st + sw_off(a_row + i * 16, a_uo));
#pragma unroll
        for (int p = 0; p < 2; p++)
            ldsm4(bh[0][p], st + TILE_B + sw_off(b_row + p * 16, b_uo));
#pragma unroll
        for (int s = 0; s < 4; s++) {
            const int cb = s & 1;
            if (s < 3) {
#pragma unroll
                for (int i = 0; i < 4; i++)
                    ldsm4(ah[cb ^ 1][i],
                          st + sw_off(a_row + i * 16, 2 * (s + 1) + a_uo));
#pragma unroll
                for (int p = 0; p < 2; p++)
                    ldsm4(bh[cb ^ 1][p],
                          st + TILE_B + sw_off(b_row + p * 16, 2 * (s + 1) + b_uo));
            }
#pragma unroll
            for (int i = 0; i < 4; i++)
#pragma unroll
                for (int j = 0; j < 4; j++)
                    mma_f16(acc[i][j], ah[cb][i],
                            &bh[cb][j >> 1][(j & 1) * 2]);
        }
    }

#pragma unroll
    for (int i = 0; i < 4; i++) {
        int row0 = rowBase + warp_m * 64 + i * 16 + (lane >> 2);
#pragma unroll
        for (int j = 0; j < 4; j++) {
            int col = colBase + warp_n * 32 + j * 8 + (lane & 3) * 2;
            float b0 = bias[col], b1 = bias[col + 1];
            float2 v0 = make_float2(acc[i][j][0] + b0, acc[i][j][1] + b1);
            float2 v1 = make_float2(acc[i][j][2] + b0, acc[i][j][3] + b1);
            *(float2*)(C + (size_t)row0 * N + col)       = v0;
            *(float2*)(C + (size_t)(row0 + 8) * N + col) = v1;
        }
    }
}

// ======================= persistent fused LSTM ==============================
__device__ __forceinline__ float sigmoidf_(float x) {
    return 1.f / (1.f + __expf(-x));
}

__global__ __launch_bounds__(256, 1)
void lstm_persist() {
    extern __shared__ float sW[];       // [8 warps][4 gates][1024]
    const int tid  = threadIdx.x;
    const int wid  = tid >> 5;
    const int lane = tid & 31;
    const int cta  = blockIdx.x;
    const int j    = cta * 8 + wid;

    for (int i = tid; i < 8192; i += 256) {
        int w   = i >> 10;
        int rem = i & 1023;
        int g   = rem >> 8;
        int q   = rem & 255;
        float4 v = *(const float4*)(g_WhT +
                     ((size_t)g * F_ + (size_t)(cta * 8 + w)) * F_ + q * 4);
        *(float4*)(sW + ((w * 4 + g) * 1024) + q * 4) = v;
    }
    __syncthreads();

    const float* sw0 = sW + (wid * 4 + 0) * 1024;
    const float* sw1 = sW + (wid * 4 + 1) * 1024;
    const float* sw2 = sW + (wid * 4 + 2) * 1024;
    const float* sw3 = sW + (wid * 4 + 3) * 1024;

    float creg = 0.f;

    for (int t = 0; t < T_; t++) {
        const float* __restrict__ hin = g_h[t & 1];
        float* __restrict__ hout      = g_h[(t + 1) & 1];

        float xg0 = 0.f, xg1 = 0.f, xg2 = 0.f, xg3 = 0.f;
        if (lane < 8) {
            size_t row = ((size_t)lane * T_ + t) * G4;
            xg0 = g_xW[row + 0 * F_ + j];
            xg1 = g_xW[row + 1 * F_ + j];
            xg2 = g_xW[row + 2 * F_ + j];
            xg3 = g_xW[row + 3 * F_ + j];
        }

        // gate dot products with packed f32x2 FMA; acc index = g*8 + b
        uint64_t acc[32];
#pragma unroll
        for (int i = 0; i < 32; i++) acc[i] = 0ull;

#pragma unroll 2
        for (int p = 0; p < 8; p++) {
            int k = (p * 32 + lane) * 4;
            ulonglong2 w0 = *(const ulonglong2*)(sw0 + k);
            ulonglong2 w1 = *(const ulonglong2*)(sw1 + k);
            ulonglong2 w2 = *(const ulonglong2*)(sw2 + k);
            ulonglong2 w3 = *(const ulonglong2*)(sw3 + k);
#pragma unroll
            for (int b = 0; b < 8; b++) {
                ulonglong2 hv = *(const ulonglong2*)(hin + b * F_ + k);
                acc[0 * 8 + b] = fma2(w0.x, hv.x, acc[0 * 8 + b]);
                acc[0 * 8 + b] = fma2(w0.y, hv.y, acc[0 * 8 + b]);
                acc[1 * 8 + b] = fma2(w1.x, hv.x, acc[1 * 8 + b]);
                acc[1 * 8 + b] = fma2(w1.y, hv.y, acc[1 * 8 + b]);
                acc[2 * 8 + b] = fma2(w2.x, hv.x, acc[2 * 8 + b]);
                acc[2 * 8 + b] = fma2(w2.y, hv.y, acc[2 * 8 + b]);
                acc[3 * 8 + b] = fma2(w3.x, hv.x, acc[3 * 8 + b]);
                acc[3 * 8 + b] = fma2(w3.y, hv.y, acc[3 * 8 + b]);
            }
        }

        float v[32];
#pragma unroll
        for (int i = 0; i < 32; i++) v[i] = unpack_add(acc[i]);

        // merging-tree warp reduce: 32 arrays x 32 lanes -> lane l holds
        // total of array l.  31 shfls vs 160 for the naive butterfly.
#pragma unroll
        for (int m = 16; m; m >>= 1) {
#pragma unroll
            for (int i = 0; i < m; i++) {
                float send = (lane & m) ? v[i] : v[i + m];
                float recv = __shfl_xor_sync(0xffffffffu, send, m);
                float keep = (lane & m) ? v[i + m] : v[i];
                v[i] = keep + recv;
            }
        }
        // lane l holds total of array l (= gate l>>3, batch l&7)
        float total = v[0];
        int bsel = lane & 7;
        float s0 = __shfl_sync(0xffffffffu, total, bsel);
        float s1 = __shfl_sync(0xffffffffu, total, 8 + bsel);
        float s2 = __shfl_sync(0xffffffffu, total, 16 + bsel);
        float s3 = __shfl_sync(0xffffffffu, total, 24 + bsel);

        if (lane < 8) {
            float zi = s0 + xg0;
            float zf = s1 + xg1;
            float zg = s2 + xg2;
            float zo = s3 + xg3;

            float cn = sigmoidf_(zf) * creg + sigmoidf_(zi) * tanhf(zg);
            float hn = sigmoidf_(zo) * tanhf(cn);
            creg = cn;

            hout[lane * F_ + j] = hn;
            g_Ah[((size_t)lane * T_ + t) * K_ + j] = __float2half_rn(hn);
        }

        __threadfence();
        __syncthreads();
        if (tid == 0) {
            atomicAdd(&g_bar, 1u);
            unsigned target = (unsigned)LSTM_CTAS * (unsigned)(t + 1);
            unsigned vv;
            do {
                asm volatile("ld.global.acquire.gpu.u32 %0, [%1];"
                             : "=r"(vv) : "l"(&g_bar));
            } while (vv < target);
        }
        __syncthreads();
    }
}

// ======================= launch =============================================
extern "C" void kernel_launch(void* const* d_in, const int* in_sizes, int n_in,
                              void* d_out, int out_size) {
    const int*   tokens = (const int*)  d_in[0];
    const float* embed  = (const float*)d_in[1];
    const float* Wx     = (const float*)d_in[2];
    const float* Wh     = (const float*)d_in[3];
    const float* bias   = (const float*)d_in[4];
    const float* Wd     = (const float*)d_in[5];
    const float* bd     = (const float*)d_in[6];
    float* out = (float*)d_out;

    float *xW = nullptr;
    __nv_bfloat16 *ahi = nullptr, *alo = nullptr, *wxh = nullptr, *wxl = nullptr;
    __half *ah = nullptr, *wdt = nullptr;
    cudaGetSymbolAddress((void**)&xW,  g_xW);
    cudaGetSymbolAddress((void**)&ahi, g_Ahi);
    cudaGetSymbolAddress((void**)&alo, g_Alo);
    cudaGetSymbolAddress((void**)&wxh, g_WxT_hi);
    cudaGetSymbolAddress((void**)&wxl, g_WxT_lo);
    cudaGetSymbolAddress((void**)&ah,  g_Ah);
    cudaGetSymbolAddress((void**)&wdt, g_WdT);

    cudaFuncSetAttribute(gemm_bf16s,
                         cudaFuncAttributeMaxDynamicSharedMemorySize, GEMM3_SMEM);
    cudaFuncSetAttribute(gemm_f16_1,
                         cudaFuncAttributeMaxDynamicSharedMemorySize, GEMM1_SMEM);
    cudaFuncSetAttribute(lstm_persist,
                         cudaFuncAttributeMaxDynamicSharedMemorySize, 131072);

    init_state<<<(B_ * F_ + 255) / 256, 256>>>();
    transpose_wh<<<dim3(G4 / 32, F_ / 32), dim3(32, 32)>>>(Wh);

    // ---- input path: x = embed[tokens]; xW = x @ Wx + b (bf16 3-product) ----
    split_rows<<<(M_ * K_ + 255) / 256, 256>>>(embed, tokens, ahi, alo);
    transpose_split<<<dim3(G4 / 32, K_ / 32), dim3(32, 8)>>>(Wx, wxh, wxl, G4);
    gemm_bf16s<<<dim3(M_ / 128, G4 / 128), 256, GEMM3_SMEM>>>(
        ahi, alo, wxh, wxl, bias, xW, G4);

    // ---- recurrence: persistent kernel, writes hs as fp16 into g_Ah ----
    lstm_persist<<<LSTM_CTAS, 256, 131072>>>();

    // ---- projection: out = hs @ Wd + bd (fp16 single product) ----
    transpose_h<<<dim3(V_ / 32, K_ / 32), dim3(32, 8)>>>(Wd, wdt, V_);
    gemm_f16_1<<<dim3(M_ / 128, V_ / 128), 256, GEMM1_SMEM>>>(
        ah, wdt, bd, out, V_);
}